// round 11
// baseline (speedup 1.0000x reference)
#include <cuda_runtime.h>
#include <cuda_bf16.h>
#include <cstdint>

constexpr int Bc=4, Nn=2048, Kc=48, Hc=128, FFc=512;
constexpr int NODES = Bc*Nn;                 // 8192
constexpr int EDGE_ROWS = NODES*Kc;          // 393216
constexpr int ROWS_T = 64;                   // edge tile rows (per warpgroup)
constexpr int N_TILES = EDGE_ROWS/ROWS_T;    // 6144
constexpr int N_STREAMS = 148*4;             // 592
constexpr float INV_SCALE = 1.0f/30.0f;

__device__ __nv_bfloat16 g_W3hi[Hc*Hc], g_W3lo[Hc*Hc];
__device__ __nv_bfloat16 g_WinHi[Hc*FFc], g_WinLo[Hc*FFc];
__device__ __nv_bfloat16 g_WoutHi[FFc*Hc], g_WoutLo[FFc*Hc];
__device__ __nv_bfloat16 g_P[NODES*Hc];        // hV @ W1a + b1 (bf16)
__device__ float g_s2[NODES*Hc];
__device__ float g_cnt[NODES];

// ---------------- low-level helpers ----------------
__device__ __forceinline__ uint32_t smem_u32(const void* p){
    uint32_t a; asm("{ .reg .u64 t; cvta.to.shared.u64 t, %1; cvt.u32.u64 %0, t; }":"=r"(a):"l"(p)); return a;
}
__device__ __forceinline__ void ldsm4(uint32_t* r, uint32_t addr){
    asm volatile("ldmatrix.sync.aligned.m8n8.x4.shared.b16 {%0,%1,%2,%3},[%4];"
        :"=r"(r[0]),"=r"(r[1]),"=r"(r[2]),"=r"(r[3]):"r"(addr));
}
__device__ __forceinline__ void ldsm4t(uint32_t* r, uint32_t addr){
    asm volatile("ldmatrix.sync.aligned.m8n8.x4.trans.shared.b16 {%0,%1,%2,%3},[%4];"
        :"=r"(r[0]),"=r"(r[1]),"=r"(r[2]),"=r"(r[3]):"r"(addr));
}
__device__ __forceinline__ void mma16816(float* d, const uint32_t* a, const uint32_t* b){
    asm volatile("mma.sync.aligned.m16n8k16.row.col.f32.bf16.bf16.f32 "
        "{%0,%1,%2,%3},{%4,%5,%6,%7},{%8,%9},{%0,%1,%2,%3};"
        :"+f"(d[0]),"+f"(d[1]),"+f"(d[2]),"+f"(d[3])
        :"r"(a[0]),"r"(a[1]),"r"(a[2]),"r"(a[3]),"r"(b[0]),"r"(b[1]));
}
__device__ __forceinline__ void cpasync16(uint32_t dst, const void* src){
    asm volatile("cp.async.cg.shared.global [%0],[%1],16;"::"r"(dst),"l"(src):"memory");
}
#define CP_COMMIT() asm volatile("cp.async.commit_group;":::"memory")
#define CP_WAIT0()  asm volatile("cp.async.wait_group 0;":::"memory")
#define BAR_WG(id) asm volatile("bar.sync %0, %1;"::"r"((id)),"r"(128):"memory")

__device__ __forceinline__ float gelu_fast(float x){
    float t1 = x*x;
    float y  = x*__fmaf_rn(0.0356774081f, t1, 0.7978845608f);
    float t; asm("tanh.approx.f32 %0, %1;":"=f"(t):"f"(y));
    float h = 0.5f*x;
    return __fmaf_rn(h, t, h);
}
__device__ __forceinline__ float gelu_erf_f(float x){ return x*normcdff(x); }

// convert half a fp32 row (64 floats) to bf16 and store to smem
__device__ __forceinline__ void cvt_halfrow(const float4* __restrict__ src, char* dst){
#pragma unroll
    for (int q=0;q<16;++q){
        float4 v = src[q];
        __nv_bfloat162 p0=__floats2bfloat162_rn(v.x,v.y), p1=__floats2bfloat162_rn(v.z,v.w);
        uint2 pk; pk.x=*reinterpret_cast<uint32_t*>(&p0); pk.y=*reinterpret_cast<uint32_t*>(&p1);
        *reinterpret_cast<uint2*>(dst + q*8) = pk;
    }
}

// ---------------- fused setup kernel: pre1 (blocks 0-127) | prep (128-383) ----------------
constexpr int P1_A = 0;
constexpr int P1_W = 17408;
constexpr int P1_B = 52224;
constexpr int P1_SMEM = 52736;
constexpr int SETUP_GRID = 384;

__global__ __launch_bounds__(256,1)
void setup_kernel(const float* __restrict__ hV,
                  const float* __restrict__ W1, const float* __restrict__ b1,
                  const float* __restrict__ W3, const float* __restrict__ Win,
                  const float* __restrict__ Wout, const float* __restrict__ mAtt){
    const int blk = blockIdx.x;
    const int tid = threadIdx.x;

    if (blk >= 128){
        // ---- prep: split weights, zero s2 ----
        int i = (blk-128)*256 + tid;   // 0..65535
        if (i < Hc*FFc){
            float v=Win[i]; __nv_bfloat16 h=__float2bfloat16(v);
            g_WinHi[i]=h; g_WinLo[i]=__float2bfloat16(v-__bfloat162float(h));
            v=Wout[i]; h=__float2bfloat16(v);
            g_WoutHi[i]=h; g_WoutLo[i]=__float2bfloat16(v-__bfloat162float(h));
        }
        if (i < Hc*Hc){
            float v=W3[i]; __nv_bfloat16 h=__float2bfloat16(v);
            g_W3hi[i]=h; g_W3lo[i]=__float2bfloat16(v-__bfloat162float(h));
        }
        float4 z=make_float4(0.f,0.f,0.f,0.f);
        float4* s2=reinterpret_cast<float4*>(g_s2);
#pragma unroll
        for (int j=0;j<4;++j) s2[i*4+j]=z;
        return;
    }

    // ---- pre1: P = hV @ W1[0:128,:] + b1 (bf16), plus cnt ----
    extern __shared__ __align__(16) char sm[];
    const int wid=tid>>5, lane=tid&31;
    const int wm=wid&1, wn=wid>>1;
    const int rowbase = blk*64;
    const uint32_t smb=smem_u32(sm);
    float* b1s = reinterpret_cast<float*>(sm+P1_B);

    if (tid<128) b1s[tid]=b1[tid];
    if (tid<64){
        float s=0.f;
        const float* mrow = mAtt + (size_t)(rowbase+tid)*Kc;
#pragma unroll 12
        for (int k=0;k<Kc;++k) s+=mrow[k];
        g_cnt[rowbase+tid]=s;
    }
    for (int i=tid;i<128*128;i+=256){
        int k=i>>7, n=i&127;
        *reinterpret_cast<__nv_bfloat16*>(sm+P1_W+k*272+n*2) = __float2bfloat16(W1[k*128+n]);
    }
    for (int e=tid;e<64*32;e+=256){
        int r=e>>5, q=e&31;
        float4 v = reinterpret_cast<const float4*>(hV + (size_t)(rowbase+r)*Hc)[q];
        __nv_bfloat162 p0=__floats2bfloat162_rn(v.x,v.y), p1=__floats2bfloat162_rn(v.z,v.w);
        uint2 pk; pk.x=*reinterpret_cast<uint32_t*>(&p0); pk.y=*reinterpret_cast<uint32_t*>(&p1);
        *reinterpret_cast<uint2*>(sm + P1_A + r*272 + q*8) = pk;
    }
    __syncthreads();

    const uint32_t a_row = smb + P1_A + (uint32_t)((wm*32 + (lane&15))*272 + (lane>>4)*16);
    const uint32_t b_row = smb + P1_W + (uint32_t)((lane&15)*272 + (wn*32 + (lane>>4)*8)*2);

    float acc[2][4][4];
#pragma unroll
    for (int s=0;s<2;++s)
#pragma unroll
        for (int j=0;j<4;++j)
#pragma unroll
            for (int c=0;c<4;++c) acc[s][j][c]=0.f;
#pragma unroll
    for (int k=0;k<8;++k){
        uint32_t A[2][4], B[2][4];
#pragma unroll
        for (int s=0;s<2;++s) ldsm4(A[s], a_row + (uint32_t)(s*16*272 + k*32));
#pragma unroll
        for (int j2=0;j2<2;++j2) ldsm4t(B[j2], b_row + (uint32_t)(k*16*272 + j2*32));
#pragma unroll
        for (int s=0;s<2;++s)
#pragma unroll
            for (int j2=0;j2<2;++j2){
                mma16816(acc[s][2*j2],   A[s], B[j2]);
                mma16816(acc[s][2*j2+1], A[s], B[j2]+2);
            }
    }
#pragma unroll
    for (int s=0;s<2;++s){
        int r0 = wm*32 + s*16 + (lane>>2);
#pragma unroll
        for (int j=0;j<4;++j){
            int c = wn*32 + j*8 + 2*(lane&3);
#pragma unroll
            for (int half=0; half<2; ++half){
                int r = r0 + half*8;
                float v0 = acc[s][j][2*half]   + b1s[c];
                float v1 = acc[s][j][2*half+1] + b1s[c+1];
                __nv_bfloat162 p=__floats2bfloat162_rn(v0,v1);
                *reinterpret_cast<uint32_t*>(&g_P[(size_t)(rowbase+r)*Hc + c]) = *reinterpret_cast<uint32_t*>(&p);
            }
        }
    }
}

// ---------------- edge MLP: 4 warpgroups x 64-row tiles, inline hE cvt + cp.async P ----------------
constexpr int OFF_BUF = 0;          // 4 wg x 2 x 17408 = 139264
constexpr int OFF_W1B = 139264;     // 34816
constexpr int OFF_W2  = 174080;     // 34816
constexpr int OFF_B2  = 208896;     // 512
constexpr int OFF_MSK = 209408;     // 4 wg x 2 parity x 64 x 4 = 2048
constexpr int EDGE_SMEM = 211456;

__global__ __launch_bounds__(512,1)
void edge_mlp_mma(const float* __restrict__ hE,
                  const int* __restrict__ eidx, const float* __restrict__ mAtt,
                  const float* __restrict__ W1, const float* __restrict__ b2,
                  const float* __restrict__ W2){
    extern __shared__ __align__(16) char sm[];
    const int tid=threadIdx.x, wid=tid>>5, lane=tid&31;
    const int wg=wid>>2, wn=wid&3;     // 4 WGs; warp tile M=64 x N=32
    const int wg_tid=tid&127;
    const uint32_t smb=smem_u32(sm);
    float* b2s=reinterpret_cast<float*>(sm+OFF_B2);
    float* msk=reinterpret_cast<float*>(sm+OFF_MSK+wg*512);   // [parity*64 + row]
    const int bufo = OFF_BUF + wg*34816;                      // + pb*17408

    for (int i=tid;i<128*128;i+=512){
        int k=i>>7, n=i&127;
        *reinterpret_cast<__nv_bfloat16*>(sm+OFF_W1B+k*272+n*2) = __float2bfloat16(W1[(128+k)*128+n]);
        *reinterpret_cast<__nv_bfloat16*>(sm+OFF_W2 +k*272+n*2) = __float2bfloat16(W2[k*128+n]);
    }
    if (tid<128) b2s[tid]=b2[tid];
    __syncthreads();

    const uint32_t a_off   = (uint32_t)((lane&15)*272 + (lane>>4)*16);
    const uint32_t w1_base = smb + OFF_W1B + (uint32_t)((lane&15)*272 + (wn*32 + (lane>>4)*8)*2);
    const uint32_t w2_base = smb + OFF_W2  + (uint32_t)((lane&15)*272 + (wn*32 + (lane>>4)*8)*2);

    float acc[4][4][4];
    int pb=0, mp=0;
    const int t0 = blockIdx.x*4+wg;
    const int prow = wg_tid>>1, phalf = wg_tid&1;   // prefetch row/half split

    // ---- prologue: fetch tile t0 (hE fp32->bf16 inline; P via cp.async) ----
    if (t0 < N_TILES){
        if (wg_tid<64) msk[wg_tid] = mAtt[t0*ROWS_T + wg_tid];
        const int ge = t0*ROWS_T + prow;
        const int node = ge / Kc;
        const int nb = eidx[ge];
        const char* sp = reinterpret_cast<const char*>(g_P) + ((size_t)((node>>11)<<11) + nb)*256 + phalf*128;
        uint32_t dP = smb + (uint32_t)(bufo + 17408 + prow*272 + phalf*128);
#pragma unroll
        for (int q=0;q<8;++q) cpasync16(dP+q*16, sp+q*16);
        CP_COMMIT();
        cvt_halfrow(reinterpret_cast<const float4*>(hE) + (size_t)ge*32 + phalf*16,
                    sm + bufo + prow*272 + phalf*128);
        CP_WAIT0();
    }
    BAR_WG(wg+1);

    for (int t = t0; t < N_TILES; t += N_STREAMS){
        const int ge_base = t*ROWS_T;
        const bool hn = (t+N_STREAMS) < N_TILES;
        const int aofft = bufo + pb*17408;          // A / M1 buffer
        const int pofft = bufo + (pb^1)*17408;      // P buffer
        const uint32_t a_base = smb + (uint32_t)aofft + a_off;

#pragma unroll
        for (int s=0;s<4;++s)
#pragma unroll
            for (int j=0;j<4;++j)
#pragma unroll
                for (int c=0;c<4;++c) acc[s][j][c]=0.f;

        // ---- GEMM1': hE x W1b (K=128) ----
#pragma unroll
        for (int k=0;k<8;++k){
            uint32_t A[4][4], B[2][4];
#pragma unroll
            for (int s=0;s<4;++s) ldsm4(A[s], a_base + (uint32_t)(s*16*272 + k*32));
#pragma unroll
            for (int j2=0;j2<2;++j2) ldsm4t(B[j2], w1_base + (uint32_t)(k*16*272 + j2*32));
#pragma unroll
            for (int s=0;s<4;++s)
#pragma unroll
                for (int j2=0;j2<2;++j2){
                    mma16816(acc[s][2*j2],   A[s], B[j2]);
                    mma16816(acc[s][2*j2+1], A[s], B[j2]+2);
                }
        }
        BAR_WG(wg+1);   // all wg warps done reading A before M1 overwrite

        // ---- epi1: M1 = gelu(acc + P) -> A buffer ----
#pragma unroll
        for (int s=0;s<4;++s){
            int r0 = s*16 + (lane>>2);
#pragma unroll
            for (int j=0;j<4;++j){
                int col = wn*32 + j*8 + 2*(lane&3);
                __nv_bfloat162 pa = *reinterpret_cast<__nv_bfloat162*>(sm + pofft + r0*272 + col*2);
                __nv_bfloat162 pc = *reinterpret_cast<__nv_bfloat162*>(sm + pofft + (r0+8)*272 + col*2);
                float x0=gelu_fast(acc[s][j][0]+__bfloat162float(pa.x));
                float x1=gelu_fast(acc[s][j][1]+__bfloat162float(pa.y));
                float x2=gelu_fast(acc[s][j][2]+__bfloat162float(pc.x));
                float x3=gelu_fast(acc[s][j][3]+__bfloat162float(pc.y));
                __nv_bfloat162 p0=__floats2bfloat162_rn(x0,x1), p1=__floats2bfloat162_rn(x2,x3);
                *reinterpret_cast<uint32_t*>(sm + aofft + r0*272 + col*2)     = *reinterpret_cast<uint32_t*>(&p0);
                *reinterpret_cast<uint32_t*>(sm + aofft + (r0+8)*272 + col*2) = *reinterpret_cast<uint32_t*>(&p1);
            }
        }
#pragma unroll
        for (int s=0;s<4;++s)
#pragma unroll
            for (int j=0;j<4;++j)
#pragma unroll
                for (int c=0;c<4;++c) acc[s][j][c]=0.f;
        BAR_WG(wg+1);   // M1 visible; P buffer free

        // ---- next tile's hE: LDG fp32 -> cvt -> STS into freed P buffer ----
        int node_n=0, nb_n=0;
        if (hn){
            const int tn = t+N_STREAMS;
            if (wg_tid<64) msk[(mp^1)*64 + wg_tid] = mAtt[tn*ROWS_T + wg_tid];
            const int ge_n = tn*ROWS_T + prow;
            node_n = ge_n / Kc;
            nb_n = eidx[ge_n];
            cvt_halfrow(reinterpret_cast<const float4*>(hE) + (size_t)ge_n*32 + phalf*16,
                        sm + pofft + prow*272 + phalf*128);
        }

        // ---- GEMM2: M1 (K=128) x W2 ----
#pragma unroll
        for (int k=0;k<8;++k){
            uint32_t A[4][4], B[2][4];
#pragma unroll
            for (int s=0;s<4;++s) ldsm4(A[s], a_base + (uint32_t)(s*16*272 + k*32));
#pragma unroll
            for (int j2=0;j2<2;++j2) ldsm4t(B[j2], w2_base + (uint32_t)(k*16*272 + j2*32));
#pragma unroll
            for (int s=0;s<4;++s)
#pragma unroll
                for (int j2=0;j2<2;++j2){
                    mma16816(acc[s][2*j2],   A[s], B[j2]);
                    mma16816(acc[s][2*j2+1], A[s], B[j2]+2);
                }
        }
        BAR_WG(wg+1);   // all wg warps done with M1 buffer

        // ---- prefetch next tile's P into freed M1 buffer ----
        if (hn){
            const char* sp = reinterpret_cast<const char*>(g_P) + ((size_t)((node_n>>11)<<11) + nb_n)*256 + phalf*128;
            uint32_t dP = smb + (uint32_t)(aofft + prow*272 + phalf*128);
#pragma unroll
            for (int q=0;q<8;++q) cpasync16(dP+q*16, sp+q*16);
            CP_COMMIT();
        }

        // ---- epi2: gelu(acc+b2)*mask, 16-row column sums -> g_s2 ----
#pragma unroll
        for (int s=0;s<4;++s){
            const int node = (ge_base + s*16)/Kc;
            const float mka = msk[mp*64 + s*16 + (lane>>2)];
            const float mkb = msk[mp*64 + s*16 + (lane>>2) + 8];
#pragma unroll
            for (int j=0;j<4;++j){
                int c = wn*32 + j*8 + 2*(lane&3);
                float2 bb = *reinterpret_cast<float2*>(&b2s[c]);
                float v0 = gelu_fast(acc[s][j][0]+bb.x)*mka;
                float v1 = gelu_fast(acc[s][j][1]+bb.y)*mka;
                float v2 = gelu_fast(acc[s][j][2]+bb.x)*mkb;
                float v3 = gelu_fast(acc[s][j][3]+bb.y)*mkb;
                float s0 = v0+v2, s1 = v1+v3;
                s0 += __shfl_xor_sync(0xffffffffu,s0,4);
                s0 += __shfl_xor_sync(0xffffffffu,s0,8);
                s0 += __shfl_xor_sync(0xffffffffu,s0,16);
                s1 += __shfl_xor_sync(0xffffffffu,s1,4);
                s1 += __shfl_xor_sync(0xffffffffu,s1,8);
                s1 += __shfl_xor_sync(0xffffffffu,s1,16);
                if (lane<4){
                    int col = wn*32 + j*8 + 2*lane;
                    atomicAdd(&g_s2[(size_t)node*Hc + col],   s0);
                    atomicAdd(&g_s2[(size_t)node*Hc + col+1], s1);
                }
            }
        }

        CP_WAIT0();
        BAR_WG(wg+1);
        pb ^= 1; mp ^= 1;
    }
}

// ---------------- fused node kernel (unchanged) ----------------
constexpr int NOFF_S2HI = 0;
constexpr int NOFF_S2LO = 17408;
constexpr int NOFF_HHI  = 34816;
constexpr int NOFF_HLO  = 52224;
constexpr int NOFF_W    = 69632;
constexpr int NOFF_B3   = 208896;
constexpr int NOFF_BIN  = 209408;
constexpr int NOFF_BOUT = 211456;
constexpr int NOFF_MV   = 211968;
constexpr int NOFF_CNT  = 212224;
constexpr int NODE_SMEM = 212480;

__global__ __launch_bounds__(256,1)
void node_kernel(const float* __restrict__ hV, const float* __restrict__ maskV,
                 const float* __restrict__ b3, const float* __restrict__ b_in,
                 const float* __restrict__ b_out, float* __restrict__ out){
    extern __shared__ __align__(16) char sm[];
    const int tid=threadIdx.x, wid=tid>>5, lane=tid&31;
    const int wm=wid&1, wn=wid>>1;
    const int rowbase = blockIdx.x*64;
    const uint32_t smb=smem_u32(sm);
    float* b3s  = reinterpret_cast<float*>(sm+NOFF_B3);
    float* bins = reinterpret_cast<float*>(sm+NOFF_BIN);
    float* bouts= reinterpret_cast<float*>(sm+NOFF_BOUT);
    float* mvs  = reinterpret_cast<float*>(sm+NOFF_MV);
    float* cnts = reinterpret_cast<float*>(sm+NOFF_CNT);

    if (tid<128) b3s[tid]=b3[tid];
    for (int i=tid;i<FFc;i+=256) bins[i]=b_in[i];
    if (tid>=128 && tid<256) bouts[tid-128]=b_out[tid-128];
    if (tid<64){ mvs[tid]=maskV[rowbase+tid]; cnts[tid]=g_cnt[rowbase+tid]; }

    for (int e=tid;e<64*32;e+=256){
        int r=e>>5, q=e&31;
        float4 v = reinterpret_cast<const float4*>(g_s2 + (size_t)(rowbase+r)*Hc)[q];
        __nv_bfloat16 hx=__float2bfloat16(v.x),hy=__float2bfloat16(v.y),
                      hz=__float2bfloat16(v.z),hw=__float2bfloat16(v.w);
        __nv_bfloat162 ph0=__halves2bfloat162(hx,hy), ph1=__halves2bfloat162(hz,hw);
        __nv_bfloat162 pl0=__floats2bfloat162_rn(v.x-__bfloat162float(hx),v.y-__bfloat162float(hy));
        __nv_bfloat162 pl1=__floats2bfloat162_rn(v.z-__bfloat162float(hz),v.w-__bfloat162float(hw));
        uint2 uh; uh.x=*reinterpret_cast<uint32_t*>(&ph0); uh.y=*reinterpret_cast<uint32_t*>(&ph1);
        uint2 ul; ul.x=*reinterpret_cast<uint32_t*>(&pl0); ul.y=*reinterpret_cast<uint32_t*>(&pl1);
        *reinterpret_cast<uint2*>(sm + NOFF_S2HI + r*272 + q*8) = uh;
        *reinterpret_cast<uint2*>(sm + NOFF_S2LO + r*272 + q*8) = ul;
    }
    for (int i=tid;i<128*16;i+=256){
        int r=i>>4, q=i&15;
        *reinterpret_cast<uint4*>(sm+NOFF_W+r*272+q*16)       = *reinterpret_cast<const uint4*>(g_W3hi + r*Hc + q*8);
        *reinterpret_cast<uint4*>(sm+NOFF_W+34816+r*272+q*16) = *reinterpret_cast<const uint4*>(g_W3lo + r*Hc + q*8);
    }
    __syncthreads();

    const uint32_t a_row = (uint32_t)((wm*32 + (lane&15))*272 + (lane>>4)*16);
    const uint32_t b_row = (uint32_t)((lane&15)*272 + (wn*32 + (lane>>4)*8)*2);

    auto gemm3 = [&](float acc[2][4][4], uint32_t ahi, uint32_t alo, uint32_t bhi, uint32_t blo){
#pragma unroll
        for (int k=0;k<8;++k){
            uint32_t Ah[2][4], Al[2][4], Bh[2][4], Bl[2][4];
#pragma unroll
            for (int s=0;s<2;++s){
                ldsm4(Ah[s], ahi + (uint32_t)(s*16*272 + k*32));
                ldsm4(Al[s], alo + (uint32_t)(s*16*272 + k*32));
            }
#pragma unroll
            for (int j2=0;j2<2;++j2){
                ldsm4t(Bh[j2], bhi + (uint32_t)(k*16*272 + j2*32));
                ldsm4t(Bl[j2], blo + (uint32_t)(k*16*272 + j2*32));
            }
#pragma unroll
            for (int s=0;s<2;++s)
#pragma unroll
                for (int j2=0;j2<2;++j2){
                    mma16816(acc[s][2*j2],   Ah[s], Bh[j2]);
                    mma16816(acc[s][2*j2+1], Ah[s], Bh[j2]+2);
                    mma16816(acc[s][2*j2],   Ah[s], Bl[j2]);
                    mma16816(acc[s][2*j2+1], Ah[s], Bl[j2]+2);
                    mma16816(acc[s][2*j2],   Al[s], Bh[j2]);
                    mma16816(acc[s][2*j2+1], Al[s], Bh[j2]+2);
                }
        }
    };

    {
        float acc[2][4][4];
#pragma unroll
        for (int s=0;s<2;++s)
#pragma unroll
            for (int j=0;j<4;++j)
#pragma unroll
                for (int c=0;c<4;++c) acc[s][j][c]=0.f;
        gemm3(acc, smb+NOFF_S2HI+a_row, smb+NOFF_S2LO+a_row,
                   smb+NOFF_W+b_row,    smb+NOFF_W+34816+b_row);
#pragma unroll
        for (int s=0;s<2;++s){
            int r0 = wm*32 + s*16 + (lane>>2);
#pragma unroll
            for (int j=0;j<4;++j){
                int c = wn*32 + j*8 + 2*(lane&3);
#pragma unroll
                for (int half=0; half<2; ++half){
                    int r = r0 + half*8;
                    size_t gi = (size_t)(rowbase+r)*Hc + c;
                    float h0 = hV[gi]   + (acc[s][j][2*half]   + cnts[r]*b3s[c])  *INV_SCALE;
                    float h1 = hV[gi+1] + (acc[s][j][2*half+1] + cnts[r]*b3s[c+1])*INV_SCALE;
                    __nv_bfloat16 x0=__float2bfloat16(h0), x1=__float2bfloat16(h1);
                    __nv_bfloat162 ph=__halves2bfloat162(x0,x1);
                    __nv_bfloat162 pl=__floats2bfloat162_rn(h0-__bfloat162float(x0),h1-__bfloat162float(x1));
                    *reinterpret_cast<uint32_t*>(sm+NOFF_HHI+r*272+c*2)=*reinterpret_cast<uint32_t*>(&ph);
                    *reinterpret_cast<uint32_t*>(sm+NOFF_HLO+r*272+c*2)=*reinterpret_cast<uint32_t*>(&pl);
                }
            }
        }
    }

    float accO[2][4][4];
#pragma unroll
    for (int s=0;s<2;++s)
#pragma unroll
        for (int j=0;j<4;++j)
#pragma unroll
            for (int c=0;c<4;++c) accO[s][j][c]=0.f;

    for (int cc=0;cc<4;++cc){
        __syncthreads();
        for (int i=tid;i<128*16;i+=256){
            int r=i>>4, q=i&15;
            *reinterpret_cast<uint4*>(sm+NOFF_W+r*272+q*16)        = *reinterpret_cast<const uint4*>(g_WinHi + r*FFc + cc*128 + q*8);
            *reinterpret_cast<uint4*>(sm+NOFF_W+34816+r*272+q*16)  = *reinterpret_cast<const uint4*>(g_WinLo + r*FFc + cc*128 + q*8);
            *reinterpret_cast<uint4*>(sm+NOFF_W+69632+r*272+q*16)  = *reinterpret_cast<const uint4*>(g_WoutHi + (size_t)(cc*128+r)*Hc + q*8);
            *reinterpret_cast<uint4*>(sm+NOFF_W+104448+r*272+q*16) = *reinterpret_cast<const uint4*>(g_WoutLo + (size_t)(cc*128+r)*Hc + q*8);
        }
        __syncthreads();

        float accM[2][4][4];
#pragma unroll
        for (int s=0;s<2;++s)
#pragma unroll
            for (int j=0;j<4;++j)
#pragma unroll
                for (int c=0;c<4;++c) accM[s][j][c]=0.f;
        gemm3(accM, smb+NOFF_HHI+a_row, smb+NOFF_HLO+a_row,
                    smb+NOFF_W+b_row,   smb+NOFF_W+34816+b_row);
#pragma unroll
        for (int s=0;s<2;++s){
            int r0 = wm*32 + s*16 + (lane>>2);
#pragma unroll
            for (int j=0;j<4;++j){
                int c = wn*32 + j*8 + 2*(lane&3);
#pragma unroll
                for (int half=0; half<2; ++half){
                    int r = r0 + half*8;
                    float v0 = gelu_erf_f(accM[s][j][2*half]   + bins[cc*128+c]);
                    float v1 = gelu_erf_f(accM[s][j][2*half+1] + bins[cc*128+c+1]);
                    __nv_bfloat16 x0=__float2bfloat16(v0), x1=__float2bfloat16(v1);
                    __nv_bfloat162 ph=__halves2bfloat162(x0,x1);
                    __nv_bfloat162 pl=__floats2bfloat162_rn(v0-__bfloat162float(x0),v1-__bfloat162float(x1));
                    *reinterpret_cast<uint32_t*>(sm+NOFF_S2HI+r*272+c*2)=*reinterpret_cast<uint32_t*>(&ph);
                    *reinterpret_cast<uint32_t*>(sm+NOFF_S2LO+r*272+c*2)=*reinterpret_cast<uint32_t*>(&pl);
                }
            }
        }
        __syncthreads();

        gemm3(accO, smb+NOFF_S2HI+a_row, smb+NOFF_S2LO+a_row,
                    smb+NOFF_W+69632+b_row, smb+NOFF_W+104448+b_row);
    }

#pragma unroll
    for (int s=0;s<2;++s){
        int r0 = wm*32 + s*16 + (lane>>2);
#pragma unroll
        for (int j=0;j<4;++j){
            int c = wn*32 + j*8 + 2*(lane&3);
#pragma unroll
            for (int half=0; half<2; ++half){
                int r = r0 + half*8;
                size_t gi = (size_t)(rowbase+r)*Hc + c;
                __nv_bfloat162 hh = *reinterpret_cast<__nv_bfloat162*>(sm+NOFF_HHI+r*272+c*2);
                __nv_bfloat162 hl = *reinterpret_cast<__nv_bfloat162*>(sm+NOFF_HLO+r*272+c*2);
                float h0 = __bfloat162float(hh.x)+__bfloat162float(hl.x);
                float h1 = __bfloat162float(hh.y)+__bfloat162float(hl.y);
                float mv = mvs[r];
                out[gi]   = (h0 + accO[s][j][2*half]   + bouts[c])  * mv;
                out[gi+1] = (h1 + accO[s][j][2*half+1] + bouts[c+1])* mv;
            }
        }
    }
}

// ---------------- launch ----------------
extern "C" void kernel_launch(void* const* d_in, const int* in_sizes, int n_in,
                              void* d_out, int out_size){
    (void)in_sizes; (void)n_in; (void)out_size;
    const float* hV   =(const float*)d_in[0];
    const float* hE   =(const float*)d_in[1];
    const int*   eidx =(const int*)d_in[2];
    const float* maskV=(const float*)d_in[3];
    const float* mAtt =(const float*)d_in[4];
    const float* W1   =(const float*)d_in[5];
    const float* b1   =(const float*)d_in[6];
    const float* W2   =(const float*)d_in[7];
    const float* b2   =(const float*)d_in[8];
    const float* W3   =(const float*)d_in[9];
    const float* b3   =(const float*)d_in[10];
    const float* Win  =(const float*)d_in[11];
    const float* binp =(const float*)d_in[12];
    const float* Wout =(const float*)d_in[13];
    const float* boutp=(const float*)d_in[14];
    float* out=(float*)d_out;

    cudaFuncSetAttribute(setup_kernel, cudaFuncAttributeMaxDynamicSharedMemorySize, P1_SMEM);
    cudaFuncSetAttribute(edge_mlp_mma, cudaFuncAttributeMaxDynamicSharedMemorySize, EDGE_SMEM);
    cudaFuncSetAttribute(node_kernel, cudaFuncAttributeMaxDynamicSharedMemorySize, NODE_SMEM);

    setup_kernel<<<SETUP_GRID, 256, P1_SMEM>>>(hV, W1, b1, W3, Win, Wout, mAtt);
    edge_mlp_mma<<<148, 512, EDGE_SMEM>>>(hE, eidx, mAtt, W1, b2, W2);
    node_kernel<<<NODES/64, 256, NODE_SMEM>>>(hV, maskV, b3, binp, boutp, out);
}

// round 12
// speedup vs baseline: 1.2089x; 1.2089x over previous
#include <cuda_runtime.h>
#include <cuda_bf16.h>
#include <cstdint>

constexpr int Bc=4, Nn=2048, Kc=48, Hc=128, FFc=512;
constexpr int NODES = Bc*Nn;                 // 8192
constexpr int EDGE_ROWS = NODES*Kc;          // 393216
constexpr int ROWS_T = 64;                   // edge tile rows (per warpgroup)
constexpr int N_TILES = EDGE_ROWS/ROWS_T;    // 6144
constexpr int N_STREAMS = 148*4;             // 592
constexpr float INV_SCALE = 1.0f/30.0f;

__device__ __nv_bfloat16 g_W3hi[Hc*Hc], g_W3lo[Hc*Hc];
__device__ __nv_bfloat16 g_WinHi[Hc*FFc], g_WinLo[Hc*FFc];
__device__ __nv_bfloat16 g_WoutHi[FFc*Hc], g_WoutLo[FFc*Hc];
__device__ __nv_bfloat16 g_P[NODES*Hc];        // hV @ W1a + b1 (bf16)
__device__ __nv_bfloat16 g_hEb[EDGE_ROWS*Hc];  // hE pre-converted to bf16
__device__ float g_s2[NODES*Hc];
__device__ float g_cnt[NODES];

// ---------------- low-level helpers ----------------
__device__ __forceinline__ uint32_t smem_u32(const void* p){
    uint32_t a; asm("{ .reg .u64 t; cvta.to.shared.u64 t, %1; cvt.u32.u64 %0, t; }":"=r"(a):"l"(p)); return a;
}
__device__ __forceinline__ void ldsm4(uint32_t* r, uint32_t addr){
    asm volatile("ldmatrix.sync.aligned.m8n8.x4.shared.b16 {%0,%1,%2,%3},[%4];"
        :"=r"(r[0]),"=r"(r[1]),"=r"(r[2]),"=r"(r[3]):"r"(addr));
}
__device__ __forceinline__ void ldsm4t(uint32_t* r, uint32_t addr){
    asm volatile("ldmatrix.sync.aligned.m8n8.x4.trans.shared.b16 {%0,%1,%2,%3},[%4];"
        :"=r"(r[0]),"=r"(r[1]),"=r"(r[2]),"=r"(r[3]):"r"(addr));
}
__device__ __forceinline__ void mma16816(float* d, const uint32_t* a, const uint32_t* b){
    asm volatile("mma.sync.aligned.m16n8k16.row.col.f32.bf16.bf16.f32 "
        "{%0,%1,%2,%3},{%4,%5,%6,%7},{%8,%9},{%0,%1,%2,%3};"
        :"+f"(d[0]),"+f"(d[1]),"+f"(d[2]),"+f"(d[3])
        :"r"(a[0]),"r"(a[1]),"r"(a[2]),"r"(a[3]),"r"(b[0]),"r"(b[1]));
}
__device__ __forceinline__ void cpasync16(uint32_t dst, const void* src){
    asm volatile("cp.async.cg.shared.global [%0],[%1],16;"::"r"(dst),"l"(src):"memory");
}
#define CP_COMMIT() asm volatile("cp.async.commit_group;":::"memory")
#define CP_WAIT0()  asm volatile("cp.async.wait_group 0;":::"memory")
#define BAR_WG(id) asm volatile("bar.sync %0, %1;"::"r"((id)),"r"(128):"memory")

__device__ __forceinline__ float gelu_fast(float x){
    float t1 = x*x;
    float y  = x*__fmaf_rn(0.0356774081f, t1, 0.7978845608f);
    float t; asm("tanh.approx.f32 %0, %1;":"=f"(t):"f"(y));
    float h = 0.5f*x;
    return __fmaf_rn(h, t, h);
}
__device__ __forceinline__ float gelu_erf_f(float x){ return x*normcdff(x); }

// ---------------- fused setup kernel: pre1 (blocks 0-127) | prep (128-383) | cvt (384+) ----------------
constexpr int P1_A = 0;
constexpr int P1_W = 17408;
constexpr int P1_B = 52224;
constexpr int P1_SMEM = 52736;
constexpr int CVT_BLOCKS = (EDGE_ROWS*Hc/4)/1024;   // 12288
constexpr int SETUP_GRID = 384 + CVT_BLOCKS;

__global__ __launch_bounds__(256,1)
void setup_kernel(const float* __restrict__ hV, const float* __restrict__ hE,
                  const float* __restrict__ W1, const float* __restrict__ b1,
                  const float* __restrict__ W3, const float* __restrict__ Win,
                  const float* __restrict__ Wout, const float* __restrict__ mAtt){
    const int blk = blockIdx.x;
    const int tid = threadIdx.x;

    if (blk >= 384){
        // ---- cvt: hE fp32 -> bf16 (1024 float4 per block) ----
        size_t base = (size_t)(blk-384)*1024;
#pragma unroll
        for (int q=0;q<4;++q){
            size_t i = base + q*256 + tid;
            float4 v = reinterpret_cast<const float4*>(hE)[i];
            __nv_bfloat162 p0=__floats2bfloat162_rn(v.x,v.y), p1=__floats2bfloat162_rn(v.z,v.w);
            uint2 pk; pk.x=*reinterpret_cast<uint32_t*>(&p0); pk.y=*reinterpret_cast<uint32_t*>(&p1);
            reinterpret_cast<uint2*>(g_hEb)[i] = pk;
        }
        return;
    }
    if (blk >= 128){
        // ---- prep: split weights, zero s2 ----
        int i = (blk-128)*256 + tid;   // 0..65535
        if (i < Hc*FFc){
            float v=Win[i]; __nv_bfloat16 h=__float2bfloat16(v);
            g_WinHi[i]=h; g_WinLo[i]=__float2bfloat16(v-__bfloat162float(h));
            v=Wout[i]; h=__float2bfloat16(v);
            g_WoutHi[i]=h; g_WoutLo[i]=__float2bfloat16(v-__bfloat162float(h));
        }
        if (i < Hc*Hc){
            float v=W3[i]; __nv_bfloat16 h=__float2bfloat16(v);
            g_W3hi[i]=h; g_W3lo[i]=__float2bfloat16(v-__bfloat162float(h));
        }
        float4 z=make_float4(0.f,0.f,0.f,0.f);
        float4* s2=reinterpret_cast<float4*>(g_s2);
#pragma unroll
        for (int j=0;j<4;++j) s2[i*4+j]=z;
        return;
    }

    // ---- pre1: P = hV @ W1[0:128,:] + b1 (bf16), plus cnt ----
    extern __shared__ __align__(16) char sm[];
    const int wid=tid>>5, lane=tid&31;
    const int wm=wid&1, wn=wid>>1;
    const int rowbase = blk*64;
    const uint32_t smb=smem_u32(sm);
    float* b1s = reinterpret_cast<float*>(sm+P1_B);

    if (tid<128) b1s[tid]=b1[tid];
    if (tid<64){
        float s=0.f;
        const float* mrow = mAtt + (size_t)(rowbase+tid)*Kc;
#pragma unroll 12
        for (int k=0;k<Kc;++k) s+=mrow[k];
        g_cnt[rowbase+tid]=s;
    }
    for (int i=tid;i<128*128;i+=256){
        int k=i>>7, n=i&127;
        *reinterpret_cast<__nv_bfloat16*>(sm+P1_W+k*272+n*2) = __float2bfloat16(W1[k*128+n]);
    }
    for (int e=tid;e<64*32;e+=256){
        int r=e>>5, q=e&31;
        float4 v = reinterpret_cast<const float4*>(hV + (size_t)(rowbase+r)*Hc)[q];
        __nv_bfloat162 p0=__floats2bfloat162_rn(v.x,v.y), p1=__floats2bfloat162_rn(v.z,v.w);
        uint2 pk; pk.x=*reinterpret_cast<uint32_t*>(&p0); pk.y=*reinterpret_cast<uint32_t*>(&p1);
        *reinterpret_cast<uint2*>(sm + P1_A + r*272 + q*8) = pk;
    }
    __syncthreads();

    const uint32_t a_row = smb + P1_A + (uint32_t)((wm*32 + (lane&15))*272 + (lane>>4)*16);
    const uint32_t b_row = smb + P1_W + (uint32_t)((lane&15)*272 + (wn*32 + (lane>>4)*8)*2);

    float acc[2][4][4];
#pragma unroll
    for (int s=0;s<2;++s)
#pragma unroll
        for (int j=0;j<4;++j)
#pragma unroll
            for (int c=0;c<4;++c) acc[s][j][c]=0.f;
#pragma unroll
    for (int k=0;k<8;++k){
        uint32_t A[2][4], B[2][4];
#pragma unroll
        for (int s=0;s<2;++s) ldsm4(A[s], a_row + (uint32_t)(s*16*272 + k*32));
#pragma unroll
        for (int j2=0;j2<2;++j2) ldsm4t(B[j2], b_row + (uint32_t)(k*16*272 + j2*32));
#pragma unroll
        for (int s=0;s<2;++s)
#pragma unroll
            for (int j2=0;j2<2;++j2){
                mma16816(acc[s][2*j2],   A[s], B[j2]);
                mma16816(acc[s][2*j2+1], A[s], B[j2]+2);
            }
    }
#pragma unroll
    for (int s=0;s<2;++s){
        int r0 = wm*32 + s*16 + (lane>>2);
#pragma unroll
        for (int j=0;j<4;++j){
            int c = wn*32 + j*8 + 2*(lane&3);
#pragma unroll
            for (int half=0; half<2; ++half){
                int r = r0 + half*8;
                float v0 = acc[s][j][2*half]   + b1s[c];
                float v1 = acc[s][j][2*half+1] + b1s[c+1];
                __nv_bfloat162 p=__floats2bfloat162_rn(v0,v1);
                *reinterpret_cast<uint32_t*>(&g_P[(size_t)(rowbase+r)*Hc + c]) = *reinterpret_cast<uint32_t*>(&p);
            }
        }
    }
}

// ---------------- edge MLP: 4 warpgroups x 64-row tiles, cp.async ping-pong (R9 exact) ----------------
constexpr int OFF_BUF = 0;          // 4 wg x 2 x 17408 = 139264
constexpr int OFF_W1B = 139264;     // 34816
constexpr int OFF_W2  = 174080;     // 34816
constexpr int OFF_B2  = 208896;     // 512
constexpr int OFF_MSK = 209408;     // 4 wg x 2 parity x 64 x 4 = 2048
constexpr int EDGE_SMEM = 211456;

__global__ __launch_bounds__(512,1)
void edge_mlp_mma(const int* __restrict__ eidx, const float* __restrict__ mAtt,
                  const float* __restrict__ W1, const float* __restrict__ b2,
                  const float* __restrict__ W2){
    extern __shared__ __align__(16) char sm[];
    const int tid=threadIdx.x, wid=tid>>5, lane=tid&31;
    const int wg=wid>>2, wn=wid&3;     // 4 WGs; warp tile M=64 x N=32
    const int wg_tid=tid&127;
    const uint32_t smb=smem_u32(sm);
    float* b2s=reinterpret_cast<float*>(sm+OFF_B2);
    float* msk=reinterpret_cast<float*>(sm+OFF_MSK+wg*512);   // [parity*64 + row]
    const int bufo = OFF_BUF + wg*34816;                      // + pb*17408

    for (int i=tid;i<128*128;i+=512){
        int k=i>>7, n=i&127;
        *reinterpret_cast<__nv_bfloat16*>(sm+OFF_W1B+k*272+n*2) = __float2bfloat16(W1[(128+k)*128+n]);
        *reinterpret_cast<__nv_bfloat16*>(sm+OFF_W2 +k*272+n*2) = __float2bfloat16(W2[k*128+n]);
    }
    if (tid<128) b2s[tid]=b2[tid];
    __syncthreads();

    const uint32_t a_off   = (uint32_t)((lane&15)*272 + (lane>>4)*16);
    const uint32_t w1_base = smb + OFF_W1B + (uint32_t)((lane&15)*272 + (wn*32 + (lane>>4)*8)*2);
    const uint32_t w2_base = smb + OFF_W2  + (uint32_t)((lane&15)*272 + (wn*32 + (lane>>4)*8)*2);

    float acc[4][4][4];
    int pb=0, mp=0;
    const int t0 = blockIdx.x*4+wg;
    const int prow = wg_tid>>1, phalf = wg_tid&1;   // prefetch row/half split

    // ---- prologue: fetch tile t0 ----
    if (t0 < N_TILES){
        if (wg_tid<64) msk[wg_tid] = mAtt[t0*ROWS_T + wg_tid];
        const int ge = t0*ROWS_T + prow;
        const int node = ge / Kc;
        const int nb = eidx[ge];
        const char* se = reinterpret_cast<const char*>(g_hEb) + (size_t)ge*256 + phalf*128;
        uint32_t dE = smb + (uint32_t)(bufo + prow*272 + phalf*128);
#pragma unroll
        for (int q=0;q<8;++q) cpasync16(dE+q*16, se+q*16);
        const char* sp = reinterpret_cast<const char*>(g_P) + ((size_t)((node>>11)<<11) + nb)*256 + phalf*128;
        uint32_t dP = smb + (uint32_t)(bufo + 17408 + prow*272 + phalf*128);
#pragma unroll
        for (int q=0;q<8;++q) cpasync16(dP+q*16, sp+q*16);
        CP_COMMIT();
        CP_WAIT0();
    }
    BAR_WG(wg+1);

    for (int t = t0; t < N_TILES; t += N_STREAMS){
        const int ge_base = t*ROWS_T;
        const bool hn = (t+N_STREAMS) < N_TILES;
        const int aofft = bufo + pb*17408;          // A / M1 buffer
        const int pofft = bufo + (pb^1)*17408;      // P buffer
        const uint32_t a_base = smb + (uint32_t)aofft + a_off;

#pragma unroll
        for (int s=0;s<4;++s)
#pragma unroll
            for (int j=0;j<4;++j)
#pragma unroll
                for (int c=0;c<4;++c) acc[s][j][c]=0.f;

        // ---- GEMM1': hE x W1b (K=128) ----
#pragma unroll
        for (int k=0;k<8;++k){
            uint32_t A[4][4], B[2][4];
#pragma unroll
            for (int s=0;s<4;++s) ldsm4(A[s], a_base + (uint32_t)(s*16*272 + k*32));
#pragma unroll
            for (int j2=0;j2<2;++j2) ldsm4t(B[j2], w1_base + (uint32_t)(k*16*272 + j2*32));
#pragma unroll
            for (int s=0;s<4;++s)
#pragma unroll
                for (int j2=0;j2<2;++j2){
                    mma16816(acc[s][2*j2],   A[s], B[j2]);
                    mma16816(acc[s][2*j2+1], A[s], B[j2]+2);
                }
        }
        BAR_WG(wg+1);   // all wg warps done reading A before M1 overwrite

        // ---- epi1: M1 = gelu(acc + P) -> A buffer ----
#pragma unroll
        for (int s=0;s<4;++s){
            int r0 = s*16 + (lane>>2);
#pragma unroll
            for (int j=0;j<4;++j){
                int col = wn*32 + j*8 + 2*(lane&3);
                __nv_bfloat162 pa = *reinterpret_cast<__nv_bfloat162*>(sm + pofft + r0*272 + col*2);
                __nv_bfloat162 pc = *reinterpret_cast<__nv_bfloat162*>(sm + pofft + (r0+8)*272 + col*2);
                float x0=gelu_fast(acc[s][j][0]+__bfloat162float(pa.x));
                float x1=gelu_fast(acc[s][j][1]+__bfloat162float(pa.y));
                float x2=gelu_fast(acc[s][j][2]+__bfloat162float(pc.x));
                float x3=gelu_fast(acc[s][j][3]+__bfloat162float(pc.y));
                __nv_bfloat162 p0=__floats2bfloat162_rn(x0,x1), p1=__floats2bfloat162_rn(x2,x3);
                *reinterpret_cast<uint32_t*>(sm + aofft + r0*272 + col*2)     = *reinterpret_cast<uint32_t*>(&p0);
                *reinterpret_cast<uint32_t*>(sm + aofft + (r0+8)*272 + col*2) = *reinterpret_cast<uint32_t*>(&p1);
            }
        }
#pragma unroll
        for (int s=0;s<4;++s)
#pragma unroll
            for (int j=0;j<4;++j)
#pragma unroll
                for (int c=0;c<4;++c) acc[s][j][c]=0.f;
        BAR_WG(wg+1);   // M1 visible; P buffer free

        // ---- prefetch next tile's hE into freed P buffer ----
        int node_n=0, nb_n=0;
        if (hn){
            const int tn = t+N_STREAMS;
            if (wg_tid<64) msk[(mp^1)*64 + wg_tid] = mAtt[tn*ROWS_T + wg_tid];
            const int ge_n = tn*ROWS_T + prow;
            node_n = ge_n / Kc;
            nb_n = eidx[ge_n];
            const char* se = reinterpret_cast<const char*>(g_hEb) + (size_t)ge_n*256 + phalf*128;
            uint32_t dE = smb + (uint32_t)(pofft + prow*272 + phalf*128);
#pragma unroll
            for (int q=0;q<8;++q) cpasync16(dE+q*16, se+q*16);
            CP_COMMIT();
        }

        // ---- GEMM2: M1 (K=128) x W2 ----
#pragma unroll
        for (int k=0;k<8;++k){
            uint32_t A[4][4], B[2][4];
#pragma unroll
            for (int s=0;s<4;++s) ldsm4(A[s], a_base + (uint32_t)(s*16*272 + k*32));
#pragma unroll
            for (int j2=0;j2<2;++j2) ldsm4t(B[j2], w2_base + (uint32_t)(k*16*272 + j2*32));
#pragma unroll
            for (int s=0;s<4;++s)
#pragma unroll
                for (int j2=0;j2<2;++j2){
                    mma16816(acc[s][2*j2],   A[s], B[j2]);
                    mma16816(acc[s][2*j2+1], A[s], B[j2]+2);
                }
        }
        BAR_WG(wg+1);   // all wg warps done with M1 buffer

        // ---- prefetch next tile's P into freed M1 buffer ----
        if (hn){
            const char* sp = reinterpret_cast<const char*>(g_P) + ((size_t)((node_n>>11)<<11) + nb_n)*256 + phalf*128;
            uint32_t dP = smb + (uint32_t)(aofft + prow*272 + phalf*128);
#pragma unroll
            for (int q=0;q<8;++q) cpasync16(dP+q*16, sp+q*16);
            CP_COMMIT();
        }

        // ---- epi2: gelu(acc+b2)*mask, 16-row column sums -> g_s2 ----
#pragma unroll
        for (int s=0;s<4;++s){
            const int node = (ge_base + s*16)/Kc;
            const float mka = msk[mp*64 + s*16 + (lane>>2)];
            const float mkb = msk[mp*64 + s*16 + (lane>>2) + 8];
#pragma unroll
            for (int j=0;j<4;++j){
                int c = wn*32 + j*8 + 2*(lane&3);
                float2 bb = *reinterpret_cast<float2*>(&b2s[c]);
                float v0 = gelu_fast(acc[s][j][0]+bb.x)*mka;
                float v1 = gelu_fast(acc[s][j][1]+bb.y)*mka;
                float v2 = gelu_fast(acc[s][j][2]+bb.x)*mkb;
                float v3 = gelu_fast(acc[s][j][3]+bb.y)*mkb;
                float s0 = v0+v2, s1 = v1+v3;
                s0 += __shfl_xor_sync(0xffffffffu,s0,4);
                s0 += __shfl_xor_sync(0xffffffffu,s0,8);
                s0 += __shfl_xor_sync(0xffffffffu,s0,16);
                s1 += __shfl_xor_sync(0xffffffffu,s1,4);
                s1 += __shfl_xor_sync(0xffffffffu,s1,8);
                s1 += __shfl_xor_sync(0xffffffffu,s1,16);
                if (lane<4){
                    int col = wn*32 + j*8 + 2*lane;
                    atomicAdd(&g_s2[(size_t)node*Hc + col],   s0);
                    atomicAdd(&g_s2[(size_t)node*Hc + col+1], s1);
                }
            }
        }

        CP_WAIT0();
        BAR_WG(wg+1);
        pb ^= 1; mp ^= 1;
    }
}

// ---------------- fused node kernel: 512 threads, 4x4 warp grid ----------------
constexpr int NOFF_S2HI = 0;
constexpr int NOFF_S2LO = 17408;
constexpr int NOFF_HHI  = 34816;
constexpr int NOFF_HLO  = 52224;
constexpr int NOFF_W    = 69632;
constexpr int NOFF_B3   = 208896;
constexpr int NOFF_BIN  = 209408;
constexpr int NOFF_BOUT = 211456;
constexpr int NOFF_MV   = 211968;
constexpr int NOFF_CNT  = 212224;
constexpr int NODE_SMEM = 212480;

__global__ __launch_bounds__(512,1)
void node_kernel(const float* __restrict__ hV, const float* __restrict__ maskV,
                 const float* __restrict__ b3, const float* __restrict__ b_in,
                 const float* __restrict__ b_out, float* __restrict__ out){
    extern __shared__ __align__(16) char sm[];
    const int tid=threadIdx.x, wid=tid>>5, lane=tid&31;
    const int wm=wid&3, wn=wid>>2;          // 4 M-tiles(16) x 4 N-tiles(32)
    const int rowbase = blockIdx.x*64;
    const uint32_t smb=smem_u32(sm);
    float* b3s  = reinterpret_cast<float*>(sm+NOFF_B3);
    float* bins = reinterpret_cast<float*>(sm+NOFF_BIN);
    float* bouts= reinterpret_cast<float*>(sm+NOFF_BOUT);
    float* mvs  = reinterpret_cast<float*>(sm+NOFF_MV);
    float* cnts = reinterpret_cast<float*>(sm+NOFF_CNT);

    if (tid<128) b3s[tid]=b3[tid];
    for (int i=tid;i<FFc;i+=512) bins[i]=b_in[i];
    if (tid>=128 && tid<256) bouts[tid-128]=b_out[tid-128];
    if (tid<64){ mvs[tid]=maskV[rowbase+tid]; cnts[tid]=g_cnt[rowbase+tid]; }

    for (int e=tid;e<64*32;e+=512){
        int r=e>>5, q=e&31;
        float4 v = reinterpret_cast<const float4*>(g_s2 + (size_t)(rowbase+r)*Hc)[q];
        __nv_bfloat16 hx=__float2bfloat16(v.x),hy=__float2bfloat16(v.y),
                      hz=__float2bfloat16(v.z),hw=__float2bfloat16(v.w);
        __nv_bfloat162 ph0=__halves2bfloat162(hx,hy), ph1=__halves2bfloat162(hz,hw);
        __nv_bfloat162 pl0=__floats2bfloat162_rn(v.x-__bfloat162float(hx),v.y-__bfloat162float(hy));
        __nv_bfloat162 pl1=__floats2bfloat162_rn(v.z-__bfloat162float(hz),v.w-__bfloat162float(hw));
        uint2 uh; uh.x=*reinterpret_cast<uint32_t*>(&ph0); uh.y=*reinterpret_cast<uint32_t*>(&ph1);
        uint2 ul; ul.x=*reinterpret_cast<uint32_t*>(&pl0); ul.y=*reinterpret_cast<uint32_t*>(&pl1);
        *reinterpret_cast<uint2*>(sm + NOFF_S2HI + r*272 + q*8) = uh;
        *reinterpret_cast<uint2*>(sm + NOFF_S2LO + r*272 + q*8) = ul;
    }
    for (int i=tid;i<128*16;i+=512){
        int r=i>>4, q=i&15;
        *reinterpret_cast<uint4*>(sm+NOFF_W+r*272+q*16)       = *reinterpret_cast<const uint4*>(g_W3hi + r*Hc + q*8);
        *reinterpret_cast<uint4*>(sm+NOFF_W+34816+r*272+q*16) = *reinterpret_cast<const uint4*>(g_W3lo + r*Hc + q*8);
    }
    __syncthreads();

    const uint32_t a_row = (uint32_t)((wm*16 + (lane&15))*272 + (lane>>4)*16);
    const uint32_t b_row = (uint32_t)((lane&15)*272 + (wn*32 + (lane>>4)*8)*2);

    auto gemm3 = [&](float acc[4][4], uint32_t ahi, uint32_t alo, uint32_t bhi, uint32_t blo){
#pragma unroll
        for (int k=0;k<8;++k){
            uint32_t Ah[4], Al[4], Bh[2][4], Bl[2][4];
            ldsm4(Ah, ahi + (uint32_t)(k*32));
            ldsm4(Al, alo + (uint32_t)(k*32));
#pragma unroll
            for (int j2=0;j2<2;++j2){
                ldsm4t(Bh[j2], bhi + (uint32_t)(k*16*272 + j2*32));
                ldsm4t(Bl[j2], blo + (uint32_t)(k*16*272 + j2*32));
            }
#pragma unroll
            for (int j2=0;j2<2;++j2){
                mma16816(acc[2*j2],   Ah, Bh[j2]);
                mma16816(acc[2*j2+1], Ah, Bh[j2]+2);
                mma16816(acc[2*j2],   Ah, Bl[j2]);
                mma16816(acc[2*j2+1], Ah, Bl[j2]+2);
                mma16816(acc[2*j2],   Al, Bh[j2]);
                mma16816(acc[2*j2+1], Al, Bh[j2]+2);
            }
        }
    };

    {
        float acc[4][4];
#pragma unroll
        for (int j=0;j<4;++j)
#pragma unroll
            for (int c=0;c<4;++c) acc[j][c]=0.f;
        gemm3(acc, smb+NOFF_S2HI+a_row, smb+NOFF_S2LO+a_row,
                   smb+NOFF_W+b_row,    smb+NOFF_W+34816+b_row);
        int r0 = wm*16 + (lane>>2);
#pragma unroll
        for (int j=0;j<4;++j){
            int c = wn*32 + j*8 + 2*(lane&3);
#pragma unroll
            for (int half=0; half<2; ++half){
                int r = r0 + half*8;
                size_t gi = (size_t)(rowbase+r)*Hc + c;
                float h0 = hV[gi]   + (acc[j][2*half]   + cnts[r]*b3s[c])  *INV_SCALE;
                float h1 = hV[gi+1] + (acc[j][2*half+1] + cnts[r]*b3s[c+1])*INV_SCALE;
                __nv_bfloat16 x0=__float2bfloat16(h0), x1=__float2bfloat16(h1);
                __nv_bfloat162 ph=__halves2bfloat162(x0,x1);
                __nv_bfloat162 pl=__floats2bfloat162_rn(h0-__bfloat162float(x0),h1-__bfloat162float(x1));
                *reinterpret_cast<uint32_t*>(sm+NOFF_HHI+r*272+c*2)=*reinterpret_cast<uint32_t*>(&ph);
                *reinterpret_cast<uint32_t*>(sm+NOFF_HLO+r*272+c*2)=*reinterpret_cast<uint32_t*>(&pl);
            }
        }
    }

    float accO[4][4];
#pragma unroll
    for (int j=0;j<4;++j)
#pragma unroll
        for (int c=0;c<4;++c) accO[j][c]=0.f;

    for (int cc=0;cc<4;++cc){
        __syncthreads();
        for (int i=tid;i<128*16;i+=512){
            int r=i>>4, q=i&15;
            *reinterpret_cast<uint4*>(sm+NOFF_W+r*272+q*16)        = *reinterpret_cast<const uint4*>(g_WinHi + r*FFc + cc*128 + q*8);
            *reinterpret_cast<uint4*>(sm+NOFF_W+34816+r*272+q*16)  = *reinterpret_cast<const uint4*>(g_WinLo + r*FFc + cc*128 + q*8);
            *reinterpret_cast<uint4*>(sm+NOFF_W+69632+r*272+q*16)  = *reinterpret_cast<const uint4*>(g_WoutHi + (size_t)(cc*128+r)*Hc + q*8);
            *reinterpret_cast<uint4*>(sm+NOFF_W+104448+r*272+q*16) = *reinterpret_cast<const uint4*>(g_WoutLo + (size_t)(cc*128+r)*Hc + q*8);
        }
        __syncthreads();

        float accM[4][4];
#pragma unroll
        for (int j=0;j<4;++j)
#pragma unroll
            for (int c=0;c<4;++c) accM[j][c]=0.f;
        gemm3(accM, smb+NOFF_HHI+a_row, smb+NOFF_HLO+a_row,
                    smb+NOFF_W+b_row,   smb+NOFF_W+34816+b_row);
        {
            int r0 = wm*16 + (lane>>2);
#pragma unroll
            for (int j=0;j<4;++j){
                int c = wn*32 + j*8 + 2*(lane&3);
#pragma unroll
                for (int half=0; half<2; ++half){
                    int r = r0 + half*8;
                    float v0 = gelu_erf_f(accM[j][2*half]   + bins[cc*128+c]);
                    float v1 = gelu_erf_f(accM[j][2*half+1] + bins[cc*128+c+1]);
                    __nv_bfloat16 x0=__float2bfloat16(v0), x1=__float2bfloat16(v1);
                    __nv_bfloat162 ph=__halves2bfloat162(x0,x1);
                    __nv_bfloat162 pl=__floats2bfloat162_rn(v0-__bfloat162float(x0),v1-__bfloat162float(x1));
                    *reinterpret_cast<uint32_t*>(sm+NOFF_S2HI+r*272+c*2)=*reinterpret_cast<uint32_t*>(&ph);
                    *reinterpret_cast<uint32_t*>(sm+NOFF_S2LO+r*272+c*2)=*reinterpret_cast<uint32_t*>(&pl);
                }
            }
        }
        __syncthreads();

        gemm3(accO, smb+NOFF_S2HI+a_row, smb+NOFF_S2LO+a_row,
                    smb+NOFF_W+69632+b_row, smb+NOFF_W+104448+b_row);
    }

    {
        int r0 = wm*16 + (lane>>2);
#pragma unroll
        for (int j=0;j<4;++j){
            int c = wn*32 + j*8 + 2*(lane&3);
#pragma unroll
            for (int half=0; half<2; ++half){
                int r = r0 + half*8;
                size_t gi = (size_t)(rowbase+r)*Hc + c;
                __nv_bfloat162 hh = *reinterpret_cast<__nv_bfloat162*>(sm+NOFF_HHI+r*272+c*2);
                __nv_bfloat162 hl = *reinterpret_cast<__nv_bfloat162*>(sm+NOFF_HLO+r*272+c*2);
                float h0 = __bfloat162float(hh.x)+__bfloat162float(hl.x);
                float h1 = __bfloat162float(hh.y)+__bfloat162float(hl.y);
                float mv = mvs[r];
                out[gi]   = (h0 + accO[j][2*half]   + bouts[c])  * mv;
                out[gi+1] = (h1 + accO[j][2*half+1] + bouts[c+1])* mv;
            }
        }
    }
}

// ---------------- launch ----------------
extern "C" void kernel_launch(void* const* d_in, const int* in_sizes, int n_in,
                              void* d_out, int out_size){
    (void)in_sizes; (void)n_in; (void)out_size;
    const float* hV   =(const float*)d_in[0];
    const float* hE   =(const float*)d_in[1];
    const int*   eidx =(const int*)d_in[2];
    const float* maskV=(const float*)d_in[3];
    const float* mAtt =(const float*)d_in[4];
    const float* W1   =(const float*)d_in[5];
    const float* b1   =(const float*)d_in[6];
    const float* W2   =(const float*)d_in[7];
    const float* b2   =(const float*)d_in[8];
    const float* W3   =(const float*)d_in[9];
    const float* b3   =(const float*)d_in[10];
    const float* Win  =(const float*)d_in[11];
    const float* binp =(const float*)d_in[12];
    const float* Wout =(const float*)d_in[13];
    const float* boutp=(const float*)d_in[14];
    float* out=(float*)d_out;

    cudaFuncSetAttribute(setup_kernel, cudaFuncAttributeMaxDynamicSharedMemorySize, P1_SMEM);
    cudaFuncSetAttribute(edge_mlp_mma, cudaFuncAttributeMaxDynamicSharedMemorySize, EDGE_SMEM);
    cudaFuncSetAttribute(node_kernel, cudaFuncAttributeMaxDynamicSharedMemorySize, NODE_SMEM);

    setup_kernel<<<SETUP_GRID, 256, P1_SMEM>>>(hV, hE, W1, b1, W3, Win, Wout, mAtt);
    edge_mlp_mma<<<148, 512, EDGE_SMEM>>>(eidx, mAtt, W1, b2, W2);
    node_kernel<<<NODES/64, 512, NODE_SMEM>>>(hV, maskV, b3, binp, boutp, out);
}

// round 13
// speedup vs baseline: 1.4576x; 1.2057x over previous
#include <cuda_runtime.h>
#include <cuda_bf16.h>
#include <cstdint>

constexpr int Bc=4, Nn=2048, Kc=48, Hc=128, FFc=512;
constexpr int NODES = Bc*Nn;                 // 8192
constexpr int ROWS_T = 48;                   // edge tile rows = 1 node
constexpr int N_TILES = NODES;               // 8192
constexpr int N_STREAMS = 148*3;             // 444
constexpr float INV_SCALE = 1.0f/30.0f;

__device__ __nv_bfloat16 g_W3hi[Hc*Hc], g_W3lo[Hc*Hc];
__device__ __nv_bfloat16 g_WinHi[Hc*FFc], g_WinLo[Hc*FFc];
__device__ __nv_bfloat16 g_WoutHi[FFc*Hc], g_WoutLo[FFc*Hc];
__device__ __nv_bfloat16 g_P[NODES*Hc];      // hV @ W1a + b1 (bf16)
__device__ float g_s2[NODES*Hc];             // fully written by edge (no atomics)
__device__ float g_cnt[NODES];

// ---------------- low-level helpers ----------------
__device__ __forceinline__ uint32_t smem_u32(const void* p){
    uint32_t a; asm("{ .reg .u64 t; cvta.to.shared.u64 t, %1; cvt.u32.u64 %0, t; }":"=r"(a):"l"(p)); return a;
}
__device__ __forceinline__ void ldsm4(uint32_t* r, uint32_t addr){
    asm volatile("ldmatrix.sync.aligned.m8n8.x4.shared.b16 {%0,%1,%2,%3},[%4];"
        :"=r"(r[0]),"=r"(r[1]),"=r"(r[2]),"=r"(r[3]):"r"(addr));
}
__device__ __forceinline__ void ldsm4t(uint32_t* r, uint32_t addr){
    asm volatile("ldmatrix.sync.aligned.m8n8.x4.trans.shared.b16 {%0,%1,%2,%3},[%4];"
        :"=r"(r[0]),"=r"(r[1]),"=r"(r[2]),"=r"(r[3]):"r"(addr));
}
__device__ __forceinline__ void mma16816(float* d, const uint32_t* a, const uint32_t* b){
    asm volatile("mma.sync.aligned.m16n8k16.row.col.f32.bf16.bf16.f32 "
        "{%0,%1,%2,%3},{%4,%5,%6,%7},{%8,%9},{%0,%1,%2,%3};"
        :"+f"(d[0]),"+f"(d[1]),"+f"(d[2]),"+f"(d[3])
        :"r"(a[0]),"r"(a[1]),"r"(a[2]),"r"(a[3]),"r"(b[0]),"r"(b[1]));
}
__device__ __forceinline__ void cpasync16(uint32_t dst, const void* src){
    asm volatile("cp.async.cg.shared.global [%0],[%1],16;"::"r"(dst),"l"(src):"memory");
}
#define CP_COMMIT() asm volatile("cp.async.commit_group;":::"memory")
#define CP_WAIT0()  asm volatile("cp.async.wait_group 0;":::"memory")
#define CP_WAIT1()  asm volatile("cp.async.wait_group 1;":::"memory")
#define BAR_WG(id) asm volatile("bar.sync %0, %1;"::"r"((id)),"r"(128):"memory")

__device__ __forceinline__ float gelu_fast(float x){
    float t1 = x*x;
    float y  = x*__fmaf_rn(0.0356774081f, t1, 0.7978845608f);
    float t; asm("tanh.approx.f32 %0, %1;":"=f"(t):"f"(y));
    float h = 0.5f*x;
    return __fmaf_rn(h, t, h);
}
__device__ __forceinline__ float gelu_erf_f(float x){ return x*normcdff(x); }

// ---------------- fused setup kernel: pre1 (blocks 0-127) | prep (128-383) ----------------
constexpr int P1_A = 0;
constexpr int P1_W = 17408;
constexpr int P1_B = 52224;
constexpr int P1_SMEM = 52736;
constexpr int SETUP_GRID = 384;

__global__ __launch_bounds__(256,1)
void setup_kernel(const float* __restrict__ hV,
                  const float* __restrict__ W1, const float* __restrict__ b1,
                  const float* __restrict__ W3, const float* __restrict__ Win,
                  const float* __restrict__ Wout, const float* __restrict__ mAtt){
    const int blk = blockIdx.x;
    const int tid = threadIdx.x;

    if (blk >= 128){
        int i = (blk-128)*256 + tid;   // 0..65535
        if (i < Hc*FFc){
            float v=Win[i]; __nv_bfloat16 h=__float2bfloat16(v);
            g_WinHi[i]=h; g_WinLo[i]=__float2bfloat16(v-__bfloat162float(h));
            v=Wout[i]; h=__float2bfloat16(v);
            g_WoutHi[i]=h; g_WoutLo[i]=__float2bfloat16(v-__bfloat162float(h));
        }
        if (i < Hc*Hc){
            float v=W3[i]; __nv_bfloat16 h=__float2bfloat16(v);
            g_W3hi[i]=h; g_W3lo[i]=__float2bfloat16(v-__bfloat162float(h));
        }
        return;
    }

    // ---- pre1: P = hV @ W1[0:128,:] + b1 (bf16), plus cnt ----
    extern __shared__ __align__(16) char sm[];
    const int wid=tid>>5, lane=tid&31;
    const int wm=wid&1, wn=wid>>1;
    const int rowbase = blk*64;
    const uint32_t smb=smem_u32(sm);
    float* b1s = reinterpret_cast<float*>(sm+P1_B);

    if (tid<128) b1s[tid]=b1[tid];
    if (tid<64){
        float s=0.f;
        const float* mrow = mAtt + (size_t)(rowbase+tid)*Kc;
#pragma unroll 12
        for (int k=0;k<Kc;++k) s+=mrow[k];
        g_cnt[rowbase+tid]=s;
    }
    for (int i=tid;i<128*128;i+=256){
        int k=i>>7, n=i&127;
        *reinterpret_cast<__nv_bfloat16*>(sm+P1_W+k*272+n*2) = __float2bfloat16(W1[k*128+n]);
    }
    for (int e=tid;e<64*32;e+=256){
        int r=e>>5, q=e&31;
        float4 v = reinterpret_cast<const float4*>(hV + (size_t)(rowbase+r)*Hc)[q];
        __nv_bfloat162 p0=__floats2bfloat162_rn(v.x,v.y), p1=__floats2bfloat162_rn(v.z,v.w);
        uint2 pk; pk.x=*reinterpret_cast<uint32_t*>(&p0); pk.y=*reinterpret_cast<uint32_t*>(&p1);
        *reinterpret_cast<uint2*>(sm + P1_A + r*272 + q*8) = pk;
    }
    __syncthreads();

    const uint32_t a_row = smb + P1_A + (uint32_t)((wm*32 + (lane&15))*272 + (lane>>4)*16);
    const uint32_t b_row = smb + P1_W + (uint32_t)((lane&15)*272 + (wn*32 + (lane>>4)*8)*2);

    float acc[2][4][4];
#pragma unroll
    for (int s=0;s<2;++s)
#pragma unroll
        for (int j=0;j<4;++j)
#pragma unroll
            for (int c=0;c<4;++c) acc[s][j][c]=0.f;
#pragma unroll
    for (int k=0;k<8;++k){
        uint32_t A[2][4], B[2][4];
#pragma unroll
        for (int s=0;s<2;++s) ldsm4(A[s], a_row + (uint32_t)(s*16*272 + k*32));
#pragma unroll
        for (int j2=0;j2<2;++j2) ldsm4t(B[j2], b_row + (uint32_t)(k*16*272 + j2*32));
#pragma unroll
        for (int s=0;s<2;++s)
#pragma unroll
            for (int j2=0;j2<2;++j2){
                mma16816(acc[s][2*j2],   A[s], B[j2]);
                mma16816(acc[s][2*j2+1], A[s], B[j2]+2);
            }
    }
#pragma unroll
    for (int s=0;s<2;++s){
        int r0 = wm*32 + s*16 + (lane>>2);
#pragma unroll
        for (int j=0;j<4;++j){
            int c = wn*32 + j*8 + 2*(lane&3);
#pragma unroll
            for (int half=0; half<2; ++half){
                int r = r0 + half*8;
                float v0 = acc[s][j][2*half]   + b1s[c];
                float v1 = acc[s][j][2*half+1] + b1s[c+1];
                __nv_bfloat162 p=__floats2bfloat162_rn(v0,v1);
                *reinterpret_cast<uint32_t*>(&g_P[(size_t)(rowbase+r)*Hc + c]) = *reinterpret_cast<uint32_t*>(&p);
            }
        }
    }
}

// ---------------- edge MLP: 3 WGs x 48-row (1-node) tiles, fp32 staging cvt ----------------
// per WG: A/M1 13056 | P 13056 | fp32 staging 24576  = 50688
constexpr int WG_SZ   = 50688;
constexpr int OFF_W1B = 152064;     // 34816
constexpr int OFF_W2  = 186880;     // 34816
constexpr int OFF_B2  = 221696;     // 512
constexpr int OFF_MSK = 222208;     // 3 x 256
constexpr int EDGE_SMEM = 222976;

__global__ __launch_bounds__(384,1)
void edge_mlp_mma(const float* __restrict__ hE,
                  const int* __restrict__ eidx, const float* __restrict__ mAtt,
                  const float* __restrict__ W1, const float* __restrict__ b2,
                  const float* __restrict__ W2){
    extern __shared__ __align__(16) char sm[];
    const int tid=threadIdx.x, wid=tid>>5, lane=tid&31;
    const int wg=wid>>2, wn=wid&3;     // 3 WGs; warp tile M=48 x N=32
    const int wg_tid=tid&127;
    const uint32_t smb=smem_u32(sm);
    float* b2s=reinterpret_cast<float*>(sm+OFF_B2);
    float* msk=reinterpret_cast<float*>(sm+OFF_MSK+wg*256);
    const int aoff = wg*WG_SZ;
    const int poff = aoff + 13056;
    const int goff = aoff + 26112;

    for (int i=tid;i<128*128;i+=384){
        int k=i>>7, n=i&127;
        *reinterpret_cast<__nv_bfloat16*>(sm+OFF_W1B+k*272+n*2) = __float2bfloat16(W1[(128+k)*128+n]);
        *reinterpret_cast<__nv_bfloat16*>(sm+OFF_W2 +k*272+n*2) = __float2bfloat16(W2[k*128+n]);
    }
    if (tid<128) b2s[tid]=b2[tid];
    __syncthreads();

    const uint32_t a_base  = smb + (uint32_t)aoff + (uint32_t)((lane&15)*272 + (lane>>4)*16);
    const uint32_t w1_base = smb + OFF_W1B + (uint32_t)((lane&15)*272 + (wn*32 + (lane>>4)*8)*2);
    const uint32_t w2_base = smb + OFF_W2  + (uint32_t)((lane&15)*272 + (wn*32 + (lane>>4)*8)*2);

    float acc[3][4][4];
    const int t0 = blockIdx.x*3+wg;
    const int prow = wg_tid>>1, phalf = wg_tid&1;

    // ---- prologue: hE(t0) -> staging -> A (bf16) ----
    {
        const char* src = reinterpret_cast<const char*>(hE) + (size_t)t0*ROWS_T*512;
#pragma unroll
        for (int q=0;q<12;++q){
            int e = wg_tid + 128*q;
            cpasync16(smb+(uint32_t)(goff+e*16), src + (size_t)e*16);
        }
        CP_COMMIT(); CP_WAIT0();
#pragma unroll
        for (int q=0;q<12;++q){
            int e = wg_tid + 128*q;
            float4 v = *reinterpret_cast<const float4*>(sm+goff+e*16);
            __nv_bfloat162 p0=__floats2bfloat162_rn(v.x,v.y), p1=__floats2bfloat162_rn(v.z,v.w);
            uint2 pk; pk.x=*reinterpret_cast<uint32_t*>(&p0); pk.y=*reinterpret_cast<uint32_t*>(&p1);
            *reinterpret_cast<uint2*>(sm + aoff + (e>>5)*272 + (e&31)*8) = pk;
        }
    }
    BAR_WG(wg+1);

    for (int t = t0; t < N_TILES; t += N_STREAMS){
        const bool hn = (t+N_STREAMS) < N_TILES;

        // ---- group 1: P(t) gather (threads 0-95) + mask ----
        if (wg_tid < 96){
            const int nb = eidx[t*Kc + prow];
            const char* sp = reinterpret_cast<const char*>(g_P)
                           + (((size_t)(t>>11)<<11) + nb)*256 + phalf*128;
            uint32_t dP = smb + (uint32_t)(poff + prow*272 + phalf*128);
#pragma unroll
            for (int q=0;q<8;++q) cpasync16(dP+q*16, sp+q*16);
        }
        if (wg_tid<48) msk[wg_tid] = mAtt[t*Kc + wg_tid];
        CP_COMMIT();
        // ---- group 2: next tile's fp32 hE -> staging ----
        if (hn){
            const char* src = reinterpret_cast<const char*>(hE) + (size_t)(t+N_STREAMS)*ROWS_T*512;
#pragma unroll
            for (int q=0;q<12;++q){
                int e = wg_tid + 128*q;
                cpasync16(smb+(uint32_t)(goff+e*16), src + (size_t)e*16);
            }
        }
        CP_COMMIT();

#pragma unroll
        for (int s=0;s<3;++s)
#pragma unroll
            for (int j=0;j<4;++j)
#pragma unroll
                for (int c=0;c<4;++c) acc[s][j][c]=0.f;

        // ---- GEMM1': hE x W1b (K=128) ----
#pragma unroll
        for (int k=0;k<8;++k){
            uint32_t A[3][4], B[2][4];
#pragma unroll
            for (int s=0;s<3;++s) ldsm4(A[s], a_base + (uint32_t)(s*16*272 + k*32));
#pragma unroll
            for (int j2=0;j2<2;++j2) ldsm4t(B[j2], w1_base + (uint32_t)(k*16*272 + j2*32));
#pragma unroll
            for (int s=0;s<3;++s)
#pragma unroll
                for (int j2=0;j2<2;++j2){
                    mma16816(acc[s][2*j2],   A[s], B[j2]);
                    mma16816(acc[s][2*j2+1], A[s], B[j2]+2);
                }
        }
        CP_WAIT1();          // P(t) arrived (own copies); BAR makes all visible
        BAR_WG(wg+1);

        // ---- epi1: M1 = gelu(acc + P) -> A buffer ----
#pragma unroll
        for (int s=0;s<3;++s){
            int r0 = s*16 + (lane>>2);
#pragma unroll
            for (int j=0;j<4;++j){
                int col = wn*32 + j*8 + 2*(lane&3);
                __nv_bfloat162 pa = *reinterpret_cast<__nv_bfloat162*>(sm + poff + r0*272 + col*2);
                __nv_bfloat162 pc = *reinterpret_cast<__nv_bfloat162*>(sm + poff + (r0+8)*272 + col*2);
                float x0=gelu_fast(acc[s][j][0]+__bfloat162float(pa.x));
                float x1=gelu_fast(acc[s][j][1]+__bfloat162float(pa.y));
                float x2=gelu_fast(acc[s][j][2]+__bfloat162float(pc.x));
                float x3=gelu_fast(acc[s][j][3]+__bfloat162float(pc.y));
                __nv_bfloat162 p0=__floats2bfloat162_rn(x0,x1), p1=__floats2bfloat162_rn(x2,x3);
                *reinterpret_cast<uint32_t*>(sm + aoff + r0*272 + col*2)     = *reinterpret_cast<uint32_t*>(&p0);
                *reinterpret_cast<uint32_t*>(sm + aoff + (r0+8)*272 + col*2) = *reinterpret_cast<uint32_t*>(&p1);
            }
        }
#pragma unroll
        for (int s=0;s<3;++s)
#pragma unroll
            for (int j=0;j<4;++j)
#pragma unroll
                for (int c=0;c<4;++c) acc[s][j][c]=0.f;
        BAR_WG(wg+1);   // M1 visible

        // ---- GEMM2: M1 (K=128) x W2 ----
#pragma unroll
        for (int k=0;k<8;++k){
            uint32_t A[3][4], B[2][4];
#pragma unroll
            for (int s=0;s<3;++s) ldsm4(A[s], a_base + (uint32_t)(s*16*272 + k*32));
#pragma unroll
            for (int j2=0;j2<2;++j2) ldsm4t(B[j2], w2_base + (uint32_t)(k*16*272 + j2*32));
#pragma unroll
            for (int s=0;s<3;++s)
#pragma unroll
                for (int j2=0;j2<2;++j2){
                    mma16816(acc[s][2*j2],   A[s], B[j2]);
                    mma16816(acc[s][2*j2+1], A[s], B[j2]+2);
                }
        }
        BAR_WG(wg+1);   // all warps done reading M1 (A buffer free)

        // ---- convert staging fp32 -> A bf16 (next tile's A) ----
        CP_WAIT0();
        if (hn){
#pragma unroll
            for (int q=0;q<12;++q){
                int e = wg_tid + 128*q;
                float4 v = *reinterpret_cast<const float4*>(sm+goff+e*16);
                __nv_bfloat162 p0=__floats2bfloat162_rn(v.x,v.y), p1=__floats2bfloat162_rn(v.z,v.w);
                uint2 pk; pk.x=*reinterpret_cast<uint32_t*>(&p0); pk.y=*reinterpret_cast<uint32_t*>(&p1);
                *reinterpret_cast<uint2*>(sm + aoff + (e>>5)*272 + (e&31)*8) = pk;
            }
        }

        // ---- epi2: gelu(acc+b2)*mask, full-node column sums -> g_s2 (plain stores) ----
        float ra[4], rb[4];
#pragma unroll
        for (int j=0;j<4;++j){ ra[j]=0.f; rb[j]=0.f; }
#pragma unroll
        for (int s=0;s<3;++s){
            const float mka = msk[s*16 + (lane>>2)];
            const float mkb = msk[s*16 + (lane>>2) + 8];
#pragma unroll
            for (int j=0;j<4;++j){
                int c = wn*32 + j*8 + 2*(lane&3);
                float2 bb = *reinterpret_cast<float2*>(&b2s[c]);
                float v0 = gelu_fast(acc[s][j][0]+bb.x)*mka;
                float v1 = gelu_fast(acc[s][j][1]+bb.y)*mka;
                float v2 = gelu_fast(acc[s][j][2]+bb.x)*mkb;
                float v3 = gelu_fast(acc[s][j][3]+bb.y)*mkb;
                ra[j] += v0+v2;
                rb[j] += v1+v3;
            }
        }
#pragma unroll
        for (int j=0;j<4;++j){
            float s0=ra[j], s1=rb[j];
            s0 += __shfl_xor_sync(0xffffffffu,s0,4);
            s0 += __shfl_xor_sync(0xffffffffu,s0,8);
            s0 += __shfl_xor_sync(0xffffffffu,s0,16);
            s1 += __shfl_xor_sync(0xffffffffu,s1,4);
            s1 += __shfl_xor_sync(0xffffffffu,s1,8);
            s1 += __shfl_xor_sync(0xffffffffu,s1,16);
            if (lane<4){
                int col = wn*32 + j*8 + 2*lane;
                g_s2[(size_t)t*Hc + col]   = s0;
                g_s2[(size_t)t*Hc + col+1] = s1;
            }
        }

        BAR_WG(wg+1);
    }
}

// ---------------- fused node kernel (R12: 512 threads, 4x4 warp grid) ----------------
constexpr int NOFF_S2HI = 0;
constexpr int NOFF_S2LO = 17408;
constexpr int NOFF_HHI  = 34816;
constexpr int NOFF_HLO  = 52224;
constexpr int NOFF_W    = 69632;
constexpr int NOFF_B3   = 208896;
constexpr int NOFF_BIN  = 209408;
constexpr int NOFF_BOUT = 211456;
constexpr int NOFF_MV   = 211968;
constexpr int NOFF_CNT  = 212224;
constexpr int NODE_SMEM = 212480;

__global__ __launch_bounds__(512,1)
void node_kernel(const float* __restrict__ hV, const float* __restrict__ maskV,
                 const float* __restrict__ b3, const float* __restrict__ b_in,
                 const float* __restrict__ b_out, float* __restrict__ out){
    extern __shared__ __align__(16) char sm[];
    const int tid=threadIdx.x, wid=tid>>5, lane=tid&31;
    const int wm=wid&3, wn=wid>>2;
    const int rowbase = blockIdx.x*64;
    const uint32_t smb=smem_u32(sm);
    float* b3s  = reinterpret_cast<float*>(sm+NOFF_B3);
    float* bins = reinterpret_cast<float*>(sm+NOFF_BIN);
    float* bouts= reinterpret_cast<float*>(sm+NOFF_BOUT);
    float* mvs  = reinterpret_cast<float*>(sm+NOFF_MV);
    float* cnts = reinterpret_cast<float*>(sm+NOFF_CNT);

    if (tid<128) b3s[tid]=b3[tid];
    for (int i=tid;i<FFc;i+=512) bins[i]=b_in[i];
    if (tid>=128 && tid<256) bouts[tid-128]=b_out[tid-128];
    if (tid<64){ mvs[tid]=maskV[rowbase+tid]; cnts[tid]=g_cnt[rowbase+tid]; }

    for (int e=tid;e<64*32;e+=512){
        int r=e>>5, q=e&31;
        float4 v = reinterpret_cast<const float4*>(g_s2 + (size_t)(rowbase+r)*Hc)[q];
        __nv_bfloat16 hx=__float2bfloat16(v.x),hy=__float2bfloat16(v.y),
                      hz=__float2bfloat16(v.z),hw=__float2bfloat16(v.w);
        __nv_bfloat162 ph0=__halves2bfloat162(hx,hy), ph1=__halves2bfloat162(hz,hw);
        __nv_bfloat162 pl0=__floats2bfloat162_rn(v.x-__bfloat162float(hx),v.y-__bfloat162float(hy));
        __nv_bfloat162 pl1=__floats2bfloat162_rn(v.z-__bfloat162float(hz),v.w-__bfloat162float(hw));
        uint2 uh; uh.x=*reinterpret_cast<uint32_t*>(&ph0); uh.y=*reinterpret_cast<uint32_t*>(&ph1);
        uint2 ul; ul.x=*reinterpret_cast<uint32_t*>(&pl0); ul.y=*reinterpret_cast<uint32_t*>(&pl1);
        *reinterpret_cast<uint2*>(sm + NOFF_S2HI + r*272 + q*8) = uh;
        *reinterpret_cast<uint2*>(sm + NOFF_S2LO + r*272 + q*8) = ul;
    }
    for (int i=tid;i<128*16;i+=512){
        int r=i>>4, q=i&15;
        *reinterpret_cast<uint4*>(sm+NOFF_W+r*272+q*16)       = *reinterpret_cast<const uint4*>(g_W3hi + r*Hc + q*8);
        *reinterpret_cast<uint4*>(sm+NOFF_W+34816+r*272+q*16) = *reinterpret_cast<const uint4*>(g_W3lo + r*Hc + q*8);
    }
    __syncthreads();

    const uint32_t a_row = (uint32_t)((wm*16 + (lane&15))*272 + (lane>>4)*16);
    const uint32_t b_row = (uint32_t)((lane&15)*272 + (wn*32 + (lane>>4)*8)*2);

    auto gemm3 = [&](float acc[4][4], uint32_t ahi, uint32_t alo, uint32_t bhi, uint32_t blo){
#pragma unroll
        for (int k=0;k<8;++k){
            uint32_t Ah[4], Al[4], Bh[2][4], Bl[2][4];
            ldsm4(Ah, ahi + (uint32_t)(k*32));
            ldsm4(Al, alo + (uint32_t)(k*32));
#pragma unroll
            for (int j2=0;j2<2;++j2){
                ldsm4t(Bh[j2], bhi + (uint32_t)(k*16*272 + j2*32));
                ldsm4t(Bl[j2], blo + (uint32_t)(k*16*272 + j2*32));
            }
#pragma unroll
            for (int j2=0;j2<2;++j2){
                mma16816(acc[2*j2],   Ah, Bh[j2]);
                mma16816(acc[2*j2+1], Ah, Bh[j2]+2);
                mma16816(acc[2*j2],   Ah, Bl[j2]);
                mma16816(acc[2*j2+1], Ah, Bl[j2]+2);
                mma16816(acc[2*j2],   Al, Bh[j2]);
                mma16816(acc[2*j2+1], Al, Bh[j2]+2);
            }
        }
    };

    {
        float acc[4][4];
#pragma unroll
        for (int j=0;j<4;++j)
#pragma unroll
            for (int c=0;c<4;++c) acc[j][c]=0.f;
        gemm3(acc, smb+NOFF_S2HI+a_row, smb+NOFF_S2LO+a_row,
                   smb+NOFF_W+b_row,    smb+NOFF_W+34816+b_row);
        int r0 = wm*16 + (lane>>2);
#pragma unroll
        for (int j=0;j<4;++j){
            int c = wn*32 + j*8 + 2*(lane&3);
#pragma unroll
            for (int half=0; half<2; ++half){
                int r = r0 + half*8;
                size_t gi = (size_t)(rowbase+r)*Hc + c;
                float h0 = hV[gi]   + (acc[j][2*half]   + cnts[r]*b3s[c])  *INV_SCALE;
                float h1 = hV[gi+1] + (acc[j][2*half+1] + cnts[r]*b3s[c+1])*INV_SCALE;
                __nv_bfloat16 x0=__float2bfloat16(h0), x1=__float2bfloat16(h1);
                __nv_bfloat162 ph=__halves2bfloat162(x0,x1);
                __nv_bfloat162 pl=__floats2bfloat162_rn(h0-__bfloat162float(x0),h1-__bfloat162float(x1));
                *reinterpret_cast<uint32_t*>(sm+NOFF_HHI+r*272+c*2)=*reinterpret_cast<uint32_t*>(&ph);
                *reinterpret_cast<uint32_t*>(sm+NOFF_HLO+r*272+c*2)=*reinterpret_cast<uint32_t*>(&pl);
            }
        }
    }

    float accO[4][4];
#pragma unroll
    for (int j=0;j<4;++j)
#pragma unroll
        for (int c=0;c<4;++c) accO[j][c]=0.f;

    for (int cc=0;cc<4;++cc){
        __syncthreads();
        for (int i=tid;i<128*16;i+=512){
            int r=i>>4, q=i&15;
            *reinterpret_cast<uint4*>(sm+NOFF_W+r*272+q*16)        = *reinterpret_cast<const uint4*>(g_WinHi + r*FFc + cc*128 + q*8);
            *reinterpret_cast<uint4*>(sm+NOFF_W+34816+r*272+q*16)  = *reinterpret_cast<const uint4*>(g_WinLo + r*FFc + cc*128 + q*8);
            *reinterpret_cast<uint4*>(sm+NOFF_W+69632+r*272+q*16)  = *reinterpret_cast<const uint4*>(g_WoutHi + (size_t)(cc*128+r)*Hc + q*8);
            *reinterpret_cast<uint4*>(sm+NOFF_W+104448+r*272+q*16) = *reinterpret_cast<const uint4*>(g_WoutLo + (size_t)(cc*128+r)*Hc + q*8);
        }
        __syncthreads();

        float accM[4][4];
#pragma unroll
        for (int j=0;j<4;++j)
#pragma unroll
            for (int c=0;c<4;++c) accM[j][c]=0.f;
        gemm3(accM, smb+NOFF_HHI+a_row, smb+NOFF_HLO+a_row,
                    smb+NOFF_W+b_row,   smb+NOFF_W+34816+b_row);
        {
            int r0 = wm*16 + (lane>>2);
#pragma unroll
            for (int j=0;j<4;++j){
                int c = wn*32 + j*8 + 2*(lane&3);
#pragma unroll
                for (int half=0; half<2; ++half){
                    int r = r0 + half*8;
                    float v0 = gelu_erf_f(accM[j][2*half]   + bins[cc*128+c]);
                    float v1 = gelu_erf_f(accM[j][2*half+1] + bins[cc*128+c+1]);
                    __nv_bfloat16 x0=__float2bfloat16(v0), x1=__float2bfloat16(v1);
                    __nv_bfloat162 ph=__halves2bfloat162(x0,x1);
                    __nv_bfloat162 pl=__floats2bfloat162_rn(v0-__bfloat162float(x0),v1-__bfloat162float(x1));
                    *reinterpret_cast<uint32_t*>(sm+NOFF_S2HI+r*272+c*2)=*reinterpret_cast<uint32_t*>(&ph);
                    *reinterpret_cast<uint32_t*>(sm+NOFF_S2LO+r*272+c*2)=*reinterpret_cast<uint32_t*>(&pl);
                }
            }
        }
        __syncthreads();

        gemm3(accO, smb+NOFF_S2HI+a_row, smb+NOFF_S2LO+a_row,
                    smb+NOFF_W+69632+b_row, smb+NOFF_W+104448+b_row);
    }

    {
        int r0 = wm*16 + (lane>>2);
#pragma unroll
        for (int j=0;j<4;++j){
            int c = wn*32 + j*8 + 2*(lane&3);
#pragma unroll
            for (int half=0; half<2; ++half){
                int r = r0 + half*8;
                size_t gi = (size_t)(rowbase+r)*Hc + c;
                __nv_bfloat162 hh = *reinterpret_cast<__nv_bfloat162*>(sm+NOFF_HHI+r*272+c*2);
                __nv_bfloat162 hl = *reinterpret_cast<__nv_bfloat162*>(sm+NOFF_HLO+r*272+c*2);
                float h0 = __bfloat162float(hh.x)+__bfloat162float(hl.x);
                float h1 = __bfloat162float(hh.y)+__bfloat162float(hl.y);
                float mv = mvs[r];
                out[gi]   = (h0 + accO[j][2*half]   + bouts[c])  * mv;
                out[gi+1] = (h1 + accO[j][2*half+1] + bouts[c+1])* mv;
            }
        }
    }
}

// ---------------- launch ----------------
extern "C" void kernel_launch(void* const* d_in, const int* in_sizes, int n_in,
                              void* d_out, int out_size){
    (void)in_sizes; (void)n_in; (void)out_size;
    const float* hV   =(const float*)d_in[0];
    const float* hE   =(const float*)d_in[1];
    const int*   eidx =(const int*)d_in[2];
    const float* maskV=(const float*)d_in[3];
    const float* mAtt =(const float*)d_in[4];
    const float* W1   =(const float*)d_in[5];
    const float* b1   =(const float*)d_in[6];
    const float* W2   =(const float*)d_in[7];
    const float* b2   =(const float*)d_in[8];
    const float* W3   =(const float*)d_in[9];
    const float* b3   =(const float*)d_in[10];
    const float* Win  =(const float*)d_in[11];
    const float* binp =(const float*)d_in[12];
    const float* Wout =(const float*)d_in[13];
    const float* boutp=(const float*)d_in[14];
    float* out=(float*)d_out;

    cudaFuncSetAttribute(setup_kernel, cudaFuncAttributeMaxDynamicSharedMemorySize, P1_SMEM);
    cudaFuncSetAttribute(edge_mlp_mma, cudaFuncAttributeMaxDynamicSharedMemorySize, EDGE_SMEM);
    cudaFuncSetAttribute(node_kernel, cudaFuncAttributeMaxDynamicSharedMemorySize, NODE_SMEM);

    setup_kernel<<<SETUP_GRID, 256, P1_SMEM>>>(hV, W1, b1, W3, Win, Wout, mAtt);
    edge_mlp_mma<<<148, 384, EDGE_SMEM>>>(hE, eidx, mAtt, W1, b2, W2);
    node_kernel<<<NODES/64, 512, NODE_SMEM>>>(hV, maskV, b3, binp, boutp, out);
}

// round 14
// speedup vs baseline: 1.5773x; 1.0821x over previous
#include <cuda_runtime.h>
#include <cuda_bf16.h>
#include <cstdint>

constexpr int Bc=4, Nn=2048, Kc=48, Hc=128, FFc=512;
constexpr int NODES = Bc*Nn;                 // 8192
constexpr int ROWS_T = 48;                   // edge tile rows = 1 node
constexpr int N_TILES = NODES;               // 8192
constexpr int N_STREAMS = 148*4;             // 592
constexpr float INV_SCALE = 1.0f/30.0f;

__device__ __nv_bfloat16 g_W3hi[Hc*Hc], g_W3lo[Hc*Hc];
__device__ __nv_bfloat16 g_WinHi[Hc*FFc], g_WinLo[Hc*FFc];
__device__ __nv_bfloat16 g_WoutHi[FFc*Hc], g_WoutLo[FFc*Hc];
__device__ __nv_bfloat16 g_P[NODES*Hc];      // hV @ W1a + b1 (bf16)
__device__ float g_s2[NODES*Hc];             // fully written by edge (no atomics)
__device__ float g_cnt[NODES];

// ---------------- low-level helpers ----------------
__device__ __forceinline__ uint32_t smem_u32(const void* p){
    uint32_t a; asm("{ .reg .u64 t; cvta.to.shared.u64 t, %1; cvt.u32.u64 %0, t; }":"=r"(a):"l"(p)); return a;
}
__device__ __forceinline__ void ldsm4(uint32_t* r, uint32_t addr){
    asm volatile("ldmatrix.sync.aligned.m8n8.x4.shared.b16 {%0,%1,%2,%3},[%4];"
        :"=r"(r[0]),"=r"(r[1]),"=r"(r[2]),"=r"(r[3]):"r"(addr));
}
__device__ __forceinline__ void ldsm4t(uint32_t* r, uint32_t addr){
    asm volatile("ldmatrix.sync.aligned.m8n8.x4.trans.shared.b16 {%0,%1,%2,%3},[%4];"
        :"=r"(r[0]),"=r"(r[1]),"=r"(r[2]),"=r"(r[3]):"r"(addr));
}
__device__ __forceinline__ void mma16816(float* d, const uint32_t* a, const uint32_t* b){
    asm volatile("mma.sync.aligned.m16n8k16.row.col.f32.bf16.bf16.f32 "
        "{%0,%1,%2,%3},{%4,%5,%6,%7},{%8,%9},{%0,%1,%2,%3};"
        :"+f"(d[0]),"+f"(d[1]),"+f"(d[2]),"+f"(d[3])
        :"r"(a[0]),"r"(a[1]),"r"(a[2]),"r"(a[3]),"r"(b[0]),"r"(b[1]));
}
__device__ __forceinline__ void cpasync16(uint32_t dst, const void* src){
    asm volatile("cp.async.cg.shared.global [%0],[%1],16;"::"r"(dst),"l"(src):"memory");
}
#define CP_COMMIT() asm volatile("cp.async.commit_group;":::"memory")
#define CP_WAIT0()  asm volatile("cp.async.wait_group 0;":::"memory")
#define BAR_WG(id) asm volatile("bar.sync %0, %1;"::"r"((id)),"r"(128):"memory")

__device__ __forceinline__ float gelu_fast(float x){
    float t1 = x*x;
    float y  = x*__fmaf_rn(0.0356774081f, t1, 0.7978845608f);
    float t; asm("tanh.approx.f32 %0, %1;":"=f"(t):"f"(y));
    float h = 0.5f*x;
    return __fmaf_rn(h, t, h);
}
__device__ __forceinline__ float gelu_erf_f(float x){ return x*normcdff(x); }

// ---------------- fused setup kernel: pre1 (blocks 0-127) | prep (128-383) ----------------
constexpr int P1_A = 0;
constexpr int P1_W = 17408;
constexpr int P1_B = 52224;
constexpr int P1_SMEM = 52736;
constexpr int SETUP_GRID = 384;

__global__ __launch_bounds__(256,1)
void setup_kernel(const float* __restrict__ hV,
                  const float* __restrict__ W1, const float* __restrict__ b1,
                  const float* __restrict__ W3, const float* __restrict__ Win,
                  const float* __restrict__ Wout, const float* __restrict__ mAtt){
    const int blk = blockIdx.x;
    const int tid = threadIdx.x;

    if (blk >= 128){
        int i = (blk-128)*256 + tid;   // 0..65535
        if (i < Hc*FFc){
            float v=Win[i]; __nv_bfloat16 h=__float2bfloat16(v);
            g_WinHi[i]=h; g_WinLo[i]=__float2bfloat16(v-__bfloat162float(h));
            v=Wout[i]; h=__float2bfloat16(v);
            g_WoutHi[i]=h; g_WoutLo[i]=__float2bfloat16(v-__bfloat162float(h));
        }
        if (i < Hc*Hc){
            float v=W3[i]; __nv_bfloat16 h=__float2bfloat16(v);
            g_W3hi[i]=h; g_W3lo[i]=__float2bfloat16(v-__bfloat162float(h));
        }
        return;
    }

    // ---- pre1: P = hV @ W1[0:128,:] + b1 (bf16), plus cnt ----
    extern __shared__ __align__(16) char sm[];
    const int wid=tid>>5, lane=tid&31;
    const int wm=wid&1, wn=wid>>1;
    const int rowbase = blk*64;
    const uint32_t smb=smem_u32(sm);
    float* b1s = reinterpret_cast<float*>(sm+P1_B);

    if (tid<128) b1s[tid]=b1[tid];
    if (tid<64){
        float s=0.f;
        const float* mrow = mAtt + (size_t)(rowbase+tid)*Kc;
#pragma unroll 12
        for (int k=0;k<Kc;++k) s+=mrow[k];
        g_cnt[rowbase+tid]=s;
    }
    for (int i=tid;i<128*128;i+=256){
        int k=i>>7, n=i&127;
        *reinterpret_cast<__nv_bfloat16*>(sm+P1_W+k*272+n*2) = __float2bfloat16(W1[k*128+n]);
    }
    for (int e=tid;e<64*32;e+=256){
        int r=e>>5, q=e&31;
        float4 v = reinterpret_cast<const float4*>(hV + (size_t)(rowbase+r)*Hc)[q];
        __nv_bfloat162 p0=__floats2bfloat162_rn(v.x,v.y), p1=__floats2bfloat162_rn(v.z,v.w);
        uint2 pk; pk.x=*reinterpret_cast<uint32_t*>(&p0); pk.y=*reinterpret_cast<uint32_t*>(&p1);
        *reinterpret_cast<uint2*>(sm + P1_A + r*272 + q*8) = pk;
    }
    __syncthreads();

    const uint32_t a_row = smb + P1_A + (uint32_t)((wm*32 + (lane&15))*272 + (lane>>4)*16);
    const uint32_t b_row = smb + P1_W + (uint32_t)((lane&15)*272 + (wn*32 + (lane>>4)*8)*2);

    float acc[2][4][4];
#pragma unroll
    for (int s=0;s<2;++s)
#pragma unroll
        for (int j=0;j<4;++j)
#pragma unroll
            for (int c=0;c<4;++c) acc[s][j][c]=0.f;
#pragma unroll
    for (int k=0;k<8;++k){
        uint32_t A[2][4], B[2][4];
#pragma unroll
        for (int s=0;s<2;++s) ldsm4(A[s], a_row + (uint32_t)(s*16*272 + k*32));
#pragma unroll
        for (int j2=0;j2<2;++j2) ldsm4t(B[j2], b_row + (uint32_t)(k*16*272 + j2*32));
#pragma unroll
        for (int s=0;s<2;++s)
#pragma unroll
            for (int j2=0;j2<2;++j2){
                mma16816(acc[s][2*j2],   A[s], B[j2]);
                mma16816(acc[s][2*j2+1], A[s], B[j2]+2);
            }
    }
#pragma unroll
    for (int s=0;s<2;++s){
        int r0 = wm*32 + s*16 + (lane>>2);
#pragma unroll
        for (int j=0;j<4;++j){
            int c = wn*32 + j*8 + 2*(lane&3);
#pragma unroll
            for (int half=0; half<2; ++half){
                int r = r0 + half*8;
                float v0 = acc[s][j][2*half]   + b1s[c];
                float v1 = acc[s][j][2*half+1] + b1s[c+1];
                __nv_bfloat162 p=__floats2bfloat162_rn(v0,v1);
                *reinterpret_cast<uint32_t*>(&g_P[(size_t)(rowbase+r)*Hc + c]) = *reinterpret_cast<uint32_t*>(&p);
            }
        }
    }
}

// ---------------- edge MLP: 4 WGs x 48-row (1-node) tiles, half-tile fp32 staging ----------------
// per WG: A/M1 13056 | P 13056 | fp32 staging (24 rows) 12288 = 38400
constexpr int WG_SZ   = 38400;
constexpr int OFF_W1B = 153600;     // 34816
constexpr int OFF_W2  = 188416;     // 34816
constexpr int OFF_B2  = 223232;     // 512
constexpr int OFF_MSK = 223744;     // 4 x 256
constexpr int EDGE_SMEM = 224768;

__global__ __launch_bounds__(512,1)
void edge_mlp_mma(const float* __restrict__ hE,
                  const int* __restrict__ eidx, const float* __restrict__ mAtt,
                  const float* __restrict__ W1, const float* __restrict__ b2,
                  const float* __restrict__ W2){
    extern __shared__ __align__(16) char sm[];
    const int tid=threadIdx.x, wid=tid>>5, lane=tid&31;
    const int wg=wid>>2, wn=wid&3;     // 4 WGs; warp tile M=48 x N=32
    const int wg_tid=tid&127;
    const uint32_t smb=smem_u32(sm);
    float* b2s=reinterpret_cast<float*>(sm+OFF_B2);
    float* msk=reinterpret_cast<float*>(sm+OFF_MSK+wg*256);
    const int aoff = wg*WG_SZ;
    const int poff = aoff + 13056;
    const int goff = aoff + 26112;

    for (int i=tid;i<128*128;i+=512){
        int k=i>>7, n=i&127;
        *reinterpret_cast<__nv_bfloat16*>(sm+OFF_W1B+k*272+n*2) = __float2bfloat16(W1[(128+k)*128+n]);
        *reinterpret_cast<__nv_bfloat16*>(sm+OFF_W2 +k*272+n*2) = __float2bfloat16(W2[k*128+n]);
    }
    if (tid<128) b2s[tid]=b2[tid];
    __syncthreads();

    const uint32_t a_base  = smb + (uint32_t)aoff + (uint32_t)((lane&15)*272 + (lane>>4)*16);
    const uint32_t w1_base = smb + OFF_W1B + (uint32_t)((lane&15)*272 + (wn*32 + (lane>>4)*8)*2);
    const uint32_t w2_base = smb + OFF_W2  + (uint32_t)((lane&15)*272 + (wn*32 + (lane>>4)*8)*2);

    float acc[3][4][4];
    const int t0 = blockIdx.x*4+wg;
    const int prow = wg_tid>>1, phalf = wg_tid&1;

    // ---- prologue: hE(t0) -> A (bf16) in two half-tile staging passes ----
#pragma unroll
    for (int h=0;h<2;++h){
        const char* src = reinterpret_cast<const char*>(hE) + ((size_t)t0*ROWS_T + h*24)*512;
#pragma unroll
        for (int q=0;q<6;++q){
            int e = wg_tid + 128*q;
            cpasync16(smb+(uint32_t)(goff+e*16), src + (size_t)e*16);
        }
        CP_COMMIT(); CP_WAIT0();
#pragma unroll
        for (int q=0;q<6;++q){
            int e = wg_tid + 128*q;
            float4 v = *reinterpret_cast<const float4*>(sm+goff+e*16);
            __nv_bfloat162 p0=__floats2bfloat162_rn(v.x,v.y), p1=__floats2bfloat162_rn(v.z,v.w);
            uint2 pk; pk.x=*reinterpret_cast<uint32_t*>(&p0); pk.y=*reinterpret_cast<uint32_t*>(&p1);
            *reinterpret_cast<uint2*>(sm + aoff + (h*24 + (e>>5))*272 + (e&31)*8) = pk;
        }
    }
    BAR_WG(wg+1);

    for (int t = t0; t < N_TILES; t += N_STREAMS){
        const bool hn = (t+N_STREAMS) < N_TILES;

        // ---- P(t) gather (threads 0-95) + mask ----
        if (wg_tid < 96){
            const int nb = eidx[t*Kc + prow];
            const char* sp = reinterpret_cast<const char*>(g_P)
                           + (((size_t)(t>>11)<<11) + nb)*256 + phalf*128;
            uint32_t dP = smb + (uint32_t)(poff + prow*272 + phalf*128);
#pragma unroll
            for (int q=0;q<8;++q) cpasync16(dP+q*16, sp+q*16);
        }
        if (wg_tid<48) msk[wg_tid] = mAtt[t*Kc + wg_tid];
        CP_COMMIT();
        // ---- F1: next tile's hE rows [0,24) -> staging ----
        if (hn){
            const char* src = reinterpret_cast<const char*>(hE) + (size_t)(t+N_STREAMS)*ROWS_T*512;
#pragma unroll
            for (int q=0;q<6;++q){
                int e = wg_tid + 128*q;
                cpasync16(smb+(uint32_t)(goff+e*16), src + (size_t)e*16);
            }
        }
        CP_COMMIT();

#pragma unroll
        for (int s=0;s<3;++s)
#pragma unroll
            for (int j=0;j<4;++j)
#pragma unroll
                for (int c=0;c<4;++c) acc[s][j][c]=0.f;

        // ---- GEMM1': hE x W1b (K=128) ----
#pragma unroll
        for (int k=0;k<8;++k){
            uint32_t A[3][4], B[2][4];
#pragma unroll
            for (int s=0;s<3;++s) ldsm4(A[s], a_base + (uint32_t)(s*16*272 + k*32));
#pragma unroll
            for (int j2=0;j2<2;++j2) ldsm4t(B[j2], w1_base + (uint32_t)(k*16*272 + j2*32));
#pragma unroll
            for (int s=0;s<3;++s)
#pragma unroll
                for (int j2=0;j2<2;++j2){
                    mma16816(acc[s][2*j2],   A[s], B[j2]);
                    mma16816(acc[s][2*j2+1], A[s], B[j2]+2);
                }
        }
        CP_WAIT0();          // P(t) + F1 arrived (own copies)
        BAR_WG(wg+1);        // all copies visible

        // ---- epi1: M1 = gelu(acc + P) -> A buffer ----
#pragma unroll
        for (int s=0;s<3;++s){
            int r0 = s*16 + (lane>>2);
#pragma unroll
            for (int j=0;j<4;++j){
                int col = wn*32 + j*8 + 2*(lane&3);
                __nv_bfloat162 pa = *reinterpret_cast<__nv_bfloat162*>(sm + poff + r0*272 + col*2);
                __nv_bfloat162 pc = *reinterpret_cast<__nv_bfloat162*>(sm + poff + (r0+8)*272 + col*2);
                float x0=gelu_fast(acc[s][j][0]+__bfloat162float(pa.x));
                float x1=gelu_fast(acc[s][j][1]+__bfloat162float(pa.y));
                float x2=gelu_fast(acc[s][j][2]+__bfloat162float(pc.x));
                float x3=gelu_fast(acc[s][j][3]+__bfloat162float(pc.y));
                __nv_bfloat162 p0=__floats2bfloat162_rn(x0,x1), p1=__floats2bfloat162_rn(x2,x3);
                *reinterpret_cast<uint32_t*>(sm + aoff + r0*272 + col*2)     = *reinterpret_cast<uint32_t*>(&p0);
                *reinterpret_cast<uint32_t*>(sm + aoff + (r0+8)*272 + col*2) = *reinterpret_cast<uint32_t*>(&p1);
            }
        }
#pragma unroll
        for (int s=0;s<3;++s)
#pragma unroll
            for (int j=0;j<4;++j)
#pragma unroll
                for (int c=0;c<4;++c) acc[s][j][c]=0.f;
        BAR_WG(wg+1);   // M1 visible

        // ---- GEMM2: M1 (K=128) x W2 ----
#pragma unroll
        for (int k=0;k<8;++k){
            uint32_t A[3][4], B[2][4];
#pragma unroll
            for (int s=0;s<3;++s) ldsm4(A[s], a_base + (uint32_t)(s*16*272 + k*32));
#pragma unroll
            for (int j2=0;j2<2;++j2) ldsm4t(B[j2], w2_base + (uint32_t)(k*16*272 + j2*32));
#pragma unroll
            for (int s=0;s<3;++s)
#pragma unroll
                for (int j2=0;j2<2;++j2){
                    mma16816(acc[s][2*j2],   A[s], B[j2]);
                    mma16816(acc[s][2*j2+1], A[s], B[j2]+2);
                }
        }
        BAR_WG(wg+1);   // all warps done reading M1 (A buffer free)

        if (hn){
            // ---- convert staging rows[0:24) -> A; issue F2 rows[24:48) ----
#pragma unroll
            for (int q=0;q<6;++q){
                int e = wg_tid + 128*q;
                float4 v = *reinterpret_cast<const float4*>(sm+goff+e*16);
                __nv_bfloat162 p0=__floats2bfloat162_rn(v.x,v.y), p1=__floats2bfloat162_rn(v.z,v.w);
                uint2 pk; pk.x=*reinterpret_cast<uint32_t*>(&p0); pk.y=*reinterpret_cast<uint32_t*>(&p1);
                *reinterpret_cast<uint2*>(sm + aoff + (e>>5)*272 + (e&31)*8) = pk;
            }
            const char* src = reinterpret_cast<const char*>(hE) + ((size_t)(t+N_STREAMS)*ROWS_T + 24)*512;
#pragma unroll
            for (int q=0;q<6;++q){
                int e = wg_tid + 128*q;
                cpasync16(smb+(uint32_t)(goff+e*16), src + (size_t)e*16);
            }
            CP_COMMIT();
        }

        // ---- epi2: gelu(acc+b2)*mask, full-node column sums -> g_s2 (plain stores) ----
        float ra[4], rb[4];
#pragma unroll
        for (int j=0;j<4;++j){ ra[j]=0.f; rb[j]=0.f; }
#pragma unroll
        for (int s=0;s<3;++s){
            const float mka = msk[s*16 + (lane>>2)];
            const float mkb = msk[s*16 + (lane>>2) + 8];
#pragma unroll
            for (int j=0;j<4;++j){
                int c = wn*32 + j*8 + 2*(lane&3);
                float2 bb = *reinterpret_cast<float2*>(&b2s[c]);
                float v0 = gelu_fast(acc[s][j][0]+bb.x)*mka;
                float v1 = gelu_fast(acc[s][j][1]+bb.y)*mka;
                float v2 = gelu_fast(acc[s][j][2]+bb.x)*mkb;
                float v3 = gelu_fast(acc[s][j][3]+bb.y)*mkb;
                ra[j] += v0+v2;
                rb[j] += v1+v3;
            }
        }
#pragma unroll
        for (int j=0;j<4;++j){
            float s0=ra[j], s1=rb[j];
            s0 += __shfl_xor_sync(0xffffffffu,s0,4);
            s0 += __shfl_xor_sync(0xffffffffu,s0,8);
            s0 += __shfl_xor_sync(0xffffffffu,s0,16);
            s1 += __shfl_xor_sync(0xffffffffu,s1,4);
            s1 += __shfl_xor_sync(0xffffffffu,s1,8);
            s1 += __shfl_xor_sync(0xffffffffu,s1,16);
            if (lane<4){
                int col = wn*32 + j*8 + 2*lane;
                g_s2[(size_t)t*Hc + col]   = s0;
                g_s2[(size_t)t*Hc + col+1] = s1;
            }
        }

        // ---- drain F2; convert staging rows[24:48) -> A ----
        if (hn){
            CP_WAIT0();
#pragma unroll
            for (int q=0;q<6;++q){
                int e = wg_tid + 128*q;
                float4 v = *reinterpret_cast<const float4*>(sm+goff+e*16);
                __nv_bfloat162 p0=__floats2bfloat162_rn(v.x,v.y), p1=__floats2bfloat162_rn(v.z,v.w);
                uint2 pk; pk.x=*reinterpret_cast<uint32_t*>(&p0); pk.y=*reinterpret_cast<uint32_t*>(&p1);
                *reinterpret_cast<uint2*>(sm + aoff + (24 + (e>>5))*272 + (e&31)*8) = pk;
            }
        }

        BAR_WG(wg+1);
    }
}

// ---------------- fused node kernel (unchanged) ----------------
constexpr int NOFF_S2HI = 0;
constexpr int NOFF_S2LO = 17408;
constexpr int NOFF_HHI  = 34816;
constexpr int NOFF_HLO  = 52224;
constexpr int NOFF_W    = 69632;
constexpr int NOFF_B3   = 208896;
constexpr int NOFF_BIN  = 209408;
constexpr int NOFF_BOUT = 211456;
constexpr int NOFF_MV   = 211968;
constexpr int NOFF_CNT  = 212224;
constexpr int NODE_SMEM = 212480;

__global__ __launch_bounds__(512,1)
void node_kernel(const float* __restrict__ hV, const float* __restrict__ maskV,
                 const float* __restrict__ b3, const float* __restrict__ b_in,
                 const float* __restrict__ b_out, float* __restrict__ out){
    extern __shared__ __align__(16) char sm[];
    const int tid=threadIdx.x, wid=tid>>5, lane=tid&31;
    const int wm=wid&3, wn=wid>>2;
    const int rowbase = blockIdx.x*64;
    const uint32_t smb=smem_u32(sm);
    float* b3s  = reinterpret_cast<float*>(sm+NOFF_B3);
    float* bins = reinterpret_cast<float*>(sm+NOFF_BIN);
    float* bouts= reinterpret_cast<float*>(sm+NOFF_BOUT);
    float* mvs  = reinterpret_cast<float*>(sm+NOFF_MV);
    float* cnts = reinterpret_cast<float*>(sm+NOFF_CNT);

    if (tid<128) b3s[tid]=b3[tid];
    for (int i=tid;i<FFc;i+=512) bins[i]=b_in[i];
    if (tid>=128 && tid<256) bouts[tid-128]=b_out[tid-128];
    if (tid<64){ mvs[tid]=maskV[rowbase+tid]; cnts[tid]=g_cnt[rowbase+tid]; }

    for (int e=tid;e<64*32;e+=512){
        int r=e>>5, q=e&31;
        float4 v = reinterpret_cast<const float4*>(g_s2 + (size_t)(rowbase+r)*Hc)[q];
        __nv_bfloat16 hx=__float2bfloat16(v.x),hy=__float2bfloat16(v.y),
                      hz=__float2bfloat16(v.z),hw=__float2bfloat16(v.w);
        __nv_bfloat162 ph0=__halves2bfloat162(hx,hy), ph1=__halves2bfloat162(hz,hw);
        __nv_bfloat162 pl0=__floats2bfloat162_rn(v.x-__bfloat162float(hx),v.y-__bfloat162float(hy));
        __nv_bfloat162 pl1=__floats2bfloat162_rn(v.z-__bfloat162float(hz),v.w-__bfloat162float(hw));
        uint2 uh; uh.x=*reinterpret_cast<uint32_t*>(&ph0); uh.y=*reinterpret_cast<uint32_t*>(&ph1);
        uint2 ul; ul.x=*reinterpret_cast<uint32_t*>(&pl0); ul.y=*reinterpret_cast<uint32_t*>(&pl1);
        *reinterpret_cast<uint2*>(sm + NOFF_S2HI + r*272 + q*8) = uh;
        *reinterpret_cast<uint2*>(sm + NOFF_S2LO + r*272 + q*8) = ul;
    }
    for (int i=tid;i<128*16;i+=512){
        int r=i>>4, q=i&15;
        *reinterpret_cast<uint4*>(sm+NOFF_W+r*272+q*16)       = *reinterpret_cast<const uint4*>(g_W3hi + r*Hc + q*8);
        *reinterpret_cast<uint4*>(sm+NOFF_W+34816+r*272+q*16) = *reinterpret_cast<const uint4*>(g_W3lo + r*Hc + q*8);
    }
    __syncthreads();

    const uint32_t a_row = (uint32_t)((wm*16 + (lane&15))*272 + (lane>>4)*16);
    const uint32_t b_row = (uint32_t)((lane&15)*272 + (wn*32 + (lane>>4)*8)*2);

    auto gemm3 = [&](float acc[4][4], uint32_t ahi, uint32_t alo, uint32_t bhi, uint32_t blo){
#pragma unroll
        for (int k=0;k<8;++k){
            uint32_t Ah[4], Al[4], Bh[2][4], Bl[2][4];
            ldsm4(Ah, ahi + (uint32_t)(k*32));
            ldsm4(Al, alo + (uint32_t)(k*32));
#pragma unroll
            for (int j2=0;j2<2;++j2){
                ldsm4t(Bh[j2], bhi + (uint32_t)(k*16*272 + j2*32));
                ldsm4t(Bl[j2], blo + (uint32_t)(k*16*272 + j2*32));
            }
#pragma unroll
            for (int j2=0;j2<2;++j2){
                mma16816(acc[2*j2],   Ah, Bh[j2]);
                mma16816(acc[2*j2+1], Ah, Bh[j2]+2);
                mma16816(acc[2*j2],   Ah, Bl[j2]);
                mma16816(acc[2*j2+1], Ah, Bl[j2]+2);
                mma16816(acc[2*j2],   Al, Bh[j2]);
                mma16816(acc[2*j2+1], Al, Bh[j2]+2);
            }
        }
    };

    {
        float acc[4][4];
#pragma unroll
        for (int j=0;j<4;++j)
#pragma unroll
            for (int c=0;c<4;++c) acc[j][c]=0.f;
        gemm3(acc, smb+NOFF_S2HI+a_row, smb+NOFF_S2LO+a_row,
                   smb+NOFF_W+b_row,    smb+NOFF_W+34816+b_row);
        int r0 = wm*16 + (lane>>2);
#pragma unroll
        for (int j=0;j<4;++j){
            int c = wn*32 + j*8 + 2*(lane&3);
#pragma unroll
            for (int half=0; half<2; ++half){
                int r = r0 + half*8;
                size_t gi = (size_t)(rowbase+r)*Hc + c;
                float h0 = hV[gi]   + (acc[j][2*half]   + cnts[r]*b3s[c])  *INV_SCALE;
                float h1 = hV[gi+1] + (acc[j][2*half+1] + cnts[r]*b3s[c+1])*INV_SCALE;
                __nv_bfloat16 x0=__float2bfloat16(h0), x1=__float2bfloat16(h1);
                __nv_bfloat162 ph=__halves2bfloat162(x0,x1);
                __nv_bfloat162 pl=__floats2bfloat162_rn(h0-__bfloat162float(x0),h1-__bfloat162float(x1));
                *reinterpret_cast<uint32_t*>(sm+NOFF_HHI+r*272+c*2)=*reinterpret_cast<uint32_t*>(&ph);
                *reinterpret_cast<uint32_t*>(sm+NOFF_HLO+r*272+c*2)=*reinterpret_cast<uint32_t*>(&pl);
            }
        }
    }

    float accO[4][4];
#pragma unroll
    for (int j=0;j<4;++j)
#pragma unroll
        for (int c=0;c<4;++c) accO[j][c]=0.f;

    for (int cc=0;cc<4;++cc){
        __syncthreads();
        for (int i=tid;i<128*16;i+=512){
            int r=i>>4, q=i&15;
            *reinterpret_cast<uint4*>(sm+NOFF_W+r*272+q*16)        = *reinterpret_cast<const uint4*>(g_WinHi + r*FFc + cc*128 + q*8);
            *reinterpret_cast<uint4*>(sm+NOFF_W+34816+r*272+q*16)  = *reinterpret_cast<const uint4*>(g_WinLo + r*FFc + cc*128 + q*8);
            *reinterpret_cast<uint4*>(sm+NOFF_W+69632+r*272+q*16)  = *reinterpret_cast<const uint4*>(g_WoutHi + (size_t)(cc*128+r)*Hc + q*8);
            *reinterpret_cast<uint4*>(sm+NOFF_W+104448+r*272+q*16) = *reinterpret_cast<const uint4*>(g_WoutLo + (size_t)(cc*128+r)*Hc + q*8);
        }
        __syncthreads();

        float accM[4][4];
#pragma unroll
        for (int j=0;j<4;++j)
#pragma unroll
            for (int c=0;c<4;++c) accM[j][c]=0.f;
        gemm3(accM, smb+NOFF_HHI+a_row, smb+NOFF_HLO+a_row,
                    smb+NOFF_W+b_row,   smb+NOFF_W+34816+b_row);
        {
            int r0 = wm*16 + (lane>>2);
#pragma unroll
            for (int j=0;j<4;++j){
                int c = wn*32 + j*8 + 2*(lane&3);
#pragma unroll
                for (int half=0; half<2; ++half){
                    int r = r0 + half*8;
                    float v0 = gelu_erf_f(accM[j][2*half]   + bins[cc*128+c]);
                    float v1 = gelu_erf_f(accM[j][2*half+1] + bins[cc*128+c+1]);
                    __nv_bfloat16 x0=__float2bfloat16(v0), x1=__float2bfloat16(v1);
                    __nv_bfloat162 ph=__halves2bfloat162(x0,x1);
                    __nv_bfloat162 pl=__floats2bfloat162_rn(v0-__bfloat162float(x0),v1-__bfloat162float(x1));
                    *reinterpret_cast<uint32_t*>(sm+NOFF_S2HI+r*272+c*2)=*reinterpret_cast<uint32_t*>(&ph);
                    *reinterpret_cast<uint32_t*>(sm+NOFF_S2LO+r*272+c*2)=*reinterpret_cast<uint32_t*>(&pl);
                }
            }
        }
        __syncthreads();

        gemm3(accO, smb+NOFF_S2HI+a_row, smb+NOFF_S2LO+a_row,
                    smb+NOFF_W+69632+b_row, smb+NOFF_W+104448+b_row);
    }

    {
        int r0 = wm*16 + (lane>>2);
#pragma unroll
        for (int j=0;j<4;++j){
            int c = wn*32 + j*8 + 2*(lane&3);
#pragma unroll
            for (int half=0; half<2; ++half){
                int r = r0 + half*8;
                size_t gi = (size_t)(rowbase+r)*Hc + c;
                __nv_bfloat162 hh = *reinterpret_cast<__nv_bfloat162*>(sm+NOFF_HHI+r*272+c*2);
                __nv_bfloat162 hl = *reinterpret_cast<__nv_bfloat162*>(sm+NOFF_HLO+r*272+c*2);
                float h0 = __bfloat162float(hh.x)+__bfloat162float(hl.x);
                float h1 = __bfloat162float(hh.y)+__bfloat162float(hl.y);
                float mv = mvs[r];
                out[gi]   = (h0 + accO[j][2*half]   + bouts[c])  * mv;
                out[gi+1] = (h1 + accO[j][2*half+1] + bouts[c+1])* mv;
            }
        }
    }
}

// ---------------- launch ----------------
extern "C" void kernel_launch(void* const* d_in, const int* in_sizes, int n_in,
                              void* d_out, int out_size){
    (void)in_sizes; (void)n_in; (void)out_size;
    const float* hV   =(const float*)d_in[0];
    const float* hE   =(const float*)d_in[1];
    const int*   eidx =(const int*)d_in[2];
    const float* maskV=(const float*)d_in[3];
    const float* mAtt =(const float*)d_in[4];
    const float* W1   =(const float*)d_in[5];
    const float* b1   =(const float*)d_in[6];
    const float* W2   =(const float*)d_in[7];
    const float* b2   =(const float*)d_in[8];
    const float* W3   =(const float*)d_in[9];
    const float* b3   =(const float*)d_in[10];
    const float* Win  =(const float*)d_in[11];
    const float* binp =(const float*)d_in[12];
    const float* Wout =(const float*)d_in[13];
    const float* boutp=(const float*)d_in[14];
    float* out=(float*)d_out;

    cudaFuncSetAttribute(setup_kernel, cudaFuncAttributeMaxDynamicSharedMemorySize, P1_SMEM);
    cudaFuncSetAttribute(edge_mlp_mma, cudaFuncAttributeMaxDynamicSharedMemorySize, EDGE_SMEM);
    cudaFuncSetAttribute(node_kernel, cudaFuncAttributeMaxDynamicSharedMemorySize, NODE_SMEM);

    setup_kernel<<<SETUP_GRID, 256, P1_SMEM>>>(hV, W1, b1, W3, Win, Wout, mAtt);
    edge_mlp_mma<<<148, 512, EDGE_SMEM>>>(hE, eidx, mAtt, W1, b2, W2);
    node_kernel<<<NODES/64, 512, NODE_SMEM>>>(hV, maskV, b3, binp, boutp, out);
}

// round 15
// speedup vs baseline: 1.5902x; 1.0082x over previous
#include <cuda_runtime.h>
#include <cuda_bf16.h>
#include <cstdint>

constexpr int Bc=4, Nn=2048, Kc=48, Hc=128, FFc=512;
constexpr int NODES = Bc*Nn;                 // 8192
constexpr int ROWS_T = 48;                   // edge tile rows = 1 node
constexpr int N_TILES = NODES;               // 8192
constexpr int N_STREAMS = 148*4;             // 592
constexpr float INV_SCALE = 1.0f/30.0f;

__device__ __nv_bfloat16 g_W3hi[Hc*Hc], g_W3lo[Hc*Hc];
__device__ __nv_bfloat16 g_WinHi[Hc*FFc], g_WinLo[Hc*FFc];
__device__ __nv_bfloat16 g_WoutHi[FFc*Hc], g_WoutLo[FFc*Hc];
__device__ __nv_bfloat16 g_P[NODES*Hc];      // hV @ W1a + b1 (bf16)
__device__ float g_s2[NODES*Hc];             // fully written by edge (no atomics)
__device__ float g_cnt[NODES];

// ---------------- low-level helpers ----------------
__device__ __forceinline__ uint32_t smem_u32(const void* p){
    uint32_t a; asm("{ .reg .u64 t; cvta.to.shared.u64 t, %1; cvt.u32.u64 %0, t; }":"=r"(a):"l"(p)); return a;
}
__device__ __forceinline__ void ldsm4(uint32_t* r, uint32_t addr){
    asm volatile("ldmatrix.sync.aligned.m8n8.x4.shared.b16 {%0,%1,%2,%3},[%4];"
        :"=r"(r[0]),"=r"(r[1]),"=r"(r[2]),"=r"(r[3]):"r"(addr));
}
__device__ __forceinline__ void ldsm4t(uint32_t* r, uint32_t addr){
    asm volatile("ldmatrix.sync.aligned.m8n8.x4.trans.shared.b16 {%0,%1,%2,%3},[%4];"
        :"=r"(r[0]),"=r"(r[1]),"=r"(r[2]),"=r"(r[3]):"r"(addr));
}
__device__ __forceinline__ void mma16816(float* d, const uint32_t* a, const uint32_t* b){
    asm volatile("mma.sync.aligned.m16n8k16.row.col.f32.bf16.bf16.f32 "
        "{%0,%1,%2,%3},{%4,%5,%6,%7},{%8,%9},{%0,%1,%2,%3};"
        :"+f"(d[0]),"+f"(d[1]),"+f"(d[2]),"+f"(d[3])
        :"r"(a[0]),"r"(a[1]),"r"(a[2]),"r"(a[3]),"r"(b[0]),"r"(b[1]));
}
__device__ __forceinline__ void cpasync16(uint32_t dst, const void* src){
    asm volatile("cp.async.cg.shared.global [%0],[%1],16;"::"r"(dst),"l"(src):"memory");
}
#define CP_COMMIT() asm volatile("cp.async.commit_group;":::"memory")
#define CP_WAIT0()  asm volatile("cp.async.wait_group 0;":::"memory")
#define BAR_WG(id) asm volatile("bar.sync %0, %1;"::"r"((id)),"r"(128):"memory")

__device__ __forceinline__ float gelu_fast(float x){
    float t1 = x*x;
    float y  = x*__fmaf_rn(0.0356774081f, t1, 0.7978845608f);
    float t; asm("tanh.approx.f32 %0, %1;":"=f"(t):"f"(y));
    float h = 0.5f*x;
    return __fmaf_rn(h, t, h);
}
__device__ __forceinline__ float gelu_erf_f(float x){ return x*normcdff(x); }

// ---------------- fused setup kernel: pre1 (blocks 0-127) | prep (128-383) ----------------
constexpr int P1_A = 0;
constexpr int P1_W = 17408;
constexpr int P1_B = 52224;
constexpr int P1_SMEM = 52736;
constexpr int SETUP_GRID = 384;

__global__ __launch_bounds__(256,1)
void setup_kernel(const float* __restrict__ hV,
                  const float* __restrict__ W1, const float* __restrict__ b1,
                  const float* __restrict__ W3, const float* __restrict__ Win,
                  const float* __restrict__ Wout, const float* __restrict__ mAtt){
    const int blk = blockIdx.x;
    const int tid = threadIdx.x;

    if (blk >= 128){
        int i = (blk-128)*256 + tid;   // 0..65535
        if (i < Hc*FFc){
            float v=Win[i]; __nv_bfloat16 h=__float2bfloat16(v);
            g_WinHi[i]=h; g_WinLo[i]=__float2bfloat16(v-__bfloat162float(h));
            v=Wout[i]; h=__float2bfloat16(v);
            g_WoutHi[i]=h; g_WoutLo[i]=__float2bfloat16(v-__bfloat162float(h));
        }
        if (i < Hc*Hc){
            float v=W3[i]; __nv_bfloat16 h=__float2bfloat16(v);
            g_W3hi[i]=h; g_W3lo[i]=__float2bfloat16(v-__bfloat162float(h));
        }
        return;
    }

    // ---- pre1: P = hV @ W1[0:128,:] + b1 (bf16), plus cnt ----
    extern __shared__ __align__(16) char sm[];
    const int wid=tid>>5, lane=tid&31;
    const int wm=wid&1, wn=wid>>1;
    const int rowbase = blk*64;
    const uint32_t smb=smem_u32(sm);
    float* b1s = reinterpret_cast<float*>(sm+P1_B);

    if (tid<128) b1s[tid]=b1[tid];
    if (tid<64){
        float s=0.f;
        const float* mrow = mAtt + (size_t)(rowbase+tid)*Kc;
#pragma unroll 12
        for (int k=0;k<Kc;++k) s+=mrow[k];
        g_cnt[rowbase+tid]=s;
    }
    for (int i=tid;i<128*128;i+=256){
        int k=i>>7, n=i&127;
        *reinterpret_cast<__nv_bfloat16*>(sm+P1_W+k*272+n*2) = __float2bfloat16(W1[k*128+n]);
    }
    for (int e=tid;e<64*32;e+=256){
        int r=e>>5, q=e&31;
        float4 v = reinterpret_cast<const float4*>(hV + (size_t)(rowbase+r)*Hc)[q];
        __nv_bfloat162 p0=__floats2bfloat162_rn(v.x,v.y), p1=__floats2bfloat162_rn(v.z,v.w);
        uint2 pk; pk.x=*reinterpret_cast<uint32_t*>(&p0); pk.y=*reinterpret_cast<uint32_t*>(&p1);
        *reinterpret_cast<uint2*>(sm + P1_A + r*272 + q*8) = pk;
    }
    __syncthreads();

    const uint32_t a_row = smb + P1_A + (uint32_t)((wm*32 + (lane&15))*272 + (lane>>4)*16);
    const uint32_t b_row = smb + P1_W + (uint32_t)((lane&15)*272 + (wn*32 + (lane>>4)*8)*2);

    float acc[2][4][4];
#pragma unroll
    for (int s=0;s<2;++s)
#pragma unroll
        for (int j=0;j<4;++j)
#pragma unroll
            for (int c=0;c<4;++c) acc[s][j][c]=0.f;
#pragma unroll
    for (int k=0;k<8;++k){
        uint32_t A[2][4], B[2][4];
#pragma unroll
        for (int s=0;s<2;++s) ldsm4(A[s], a_row + (uint32_t)(s*16*272 + k*32));
#pragma unroll
        for (int j2=0;j2<2;++j2) ldsm4t(B[j2], b_row + (uint32_t)(k*16*272 + j2*32));
#pragma unroll
        for (int s=0;s<2;++s)
#pragma unroll
            for (int j2=0;j2<2;++j2){
                mma16816(acc[s][2*j2],   A[s], B[j2]);
                mma16816(acc[s][2*j2+1], A[s], B[j2]+2);
            }
    }
#pragma unroll
    for (int s=0;s<2;++s){
        int r0 = wm*32 + s*16 + (lane>>2);
#pragma unroll
        for (int j=0;j<4;++j){
            int c = wn*32 + j*8 + 2*(lane&3);
#pragma unroll
            for (int half=0; half<2; ++half){
                int r = r0 + half*8;
                float v0 = acc[s][j][2*half]   + b1s[c];
                float v1 = acc[s][j][2*half+1] + b1s[c+1];
                __nv_bfloat162 p=__floats2bfloat162_rn(v0,v1);
                *reinterpret_cast<uint32_t*>(&g_P[(size_t)(rowbase+r)*Hc + c]) = *reinterpret_cast<uint32_t*>(&p);
            }
        }
    }
}

// ---------------- edge MLP: 4 WGs x 48-row (1-node) tiles, half-tile fp32 staging (R14 exact) ----------------
constexpr int WG_SZ   = 38400;
constexpr int OFF_W1B = 153600;     // 34816
constexpr int OFF_W2  = 188416;     // 34816
constexpr int OFF_B2  = 223232;     // 512
constexpr int OFF_MSK = 223744;     // 4 x 256
constexpr int EDGE_SMEM = 224768;

__global__ __launch_bounds__(512,1)
void edge_mlp_mma(const float* __restrict__ hE,
                  const int* __restrict__ eidx, const float* __restrict__ mAtt,
                  const float* __restrict__ W1, const float* __restrict__ b2,
                  const float* __restrict__ W2){
    extern __shared__ __align__(16) char sm[];
    const int tid=threadIdx.x, wid=tid>>5, lane=tid&31;
    const int wg=wid>>2, wn=wid&3;     // 4 WGs; warp tile M=48 x N=32
    const int wg_tid=tid&127;
    const uint32_t smb=smem_u32(sm);
    float* b2s=reinterpret_cast<float*>(sm+OFF_B2);
    float* msk=reinterpret_cast<float*>(sm+OFF_MSK+wg*256);
    const int aoff = wg*WG_SZ;
    const int poff = aoff + 13056;
    const int goff = aoff + 26112;

    for (int i=tid;i<128*128;i+=512){
        int k=i>>7, n=i&127;
        *reinterpret_cast<__nv_bfloat16*>(sm+OFF_W1B+k*272+n*2) = __float2bfloat16(W1[(128+k)*128+n]);
        *reinterpret_cast<__nv_bfloat16*>(sm+OFF_W2 +k*272+n*2) = __float2bfloat16(W2[k*128+n]);
    }
    if (tid<128) b2s[tid]=b2[tid];
    __syncthreads();

    const uint32_t a_base  = smb + (uint32_t)aoff + (uint32_t)((lane&15)*272 + (lane>>4)*16);
    const uint32_t w1_base = smb + OFF_W1B + (uint32_t)((lane&15)*272 + (wn*32 + (lane>>4)*8)*2);
    const uint32_t w2_base = smb + OFF_W2  + (uint32_t)((lane&15)*272 + (wn*32 + (lane>>4)*8)*2);

    float acc[3][4][4];
    const int t0 = blockIdx.x*4+wg;
    const int prow = wg_tid>>1, phalf = wg_tid&1;

    // ---- prologue: hE(t0) -> A (bf16) in two half-tile staging passes ----
#pragma unroll
    for (int h=0;h<2;++h){
        const char* src = reinterpret_cast<const char*>(hE) + ((size_t)t0*ROWS_T + h*24)*512;
#pragma unroll
        for (int q=0;q<6;++q){
            int e = wg_tid + 128*q;
            cpasync16(smb+(uint32_t)(goff+e*16), src + (size_t)e*16);
        }
        CP_COMMIT(); CP_WAIT0();
#pragma unroll
        for (int q=0;q<6;++q){
            int e = wg_tid + 128*q;
            float4 v = *reinterpret_cast<const float4*>(sm+goff+e*16);
            __nv_bfloat162 p0=__floats2bfloat162_rn(v.x,v.y), p1=__floats2bfloat162_rn(v.z,v.w);
            uint2 pk; pk.x=*reinterpret_cast<uint32_t*>(&p0); pk.y=*reinterpret_cast<uint32_t*>(&p1);
            *reinterpret_cast<uint2*>(sm + aoff + (h*24 + (e>>5))*272 + (e&31)*8) = pk;
        }
    }
    BAR_WG(wg+1);

    for (int t = t0; t < N_TILES; t += N_STREAMS){
        const bool hn = (t+N_STREAMS) < N_TILES;

        // ---- P(t) gather (threads 0-95) + mask ----
        if (wg_tid < 96){
            const int nb = eidx[t*Kc + prow];
            const char* sp = reinterpret_cast<const char*>(g_P)
                           + (((size_t)(t>>11)<<11) + nb)*256 + phalf*128;
            uint32_t dP = smb + (uint32_t)(poff + prow*272 + phalf*128);
#pragma unroll
            for (int q=0;q<8;++q) cpasync16(dP+q*16, sp+q*16);
        }
        if (wg_tid<48) msk[wg_tid] = mAtt[t*Kc + wg_tid];
        CP_COMMIT();
        // ---- F1: next tile's hE rows [0,24) -> staging ----
        if (hn){
            const char* src = reinterpret_cast<const char*>(hE) + (size_t)(t+N_STREAMS)*ROWS_T*512;
#pragma unroll
            for (int q=0;q<6;++q){
                int e = wg_tid + 128*q;
                cpasync16(smb+(uint32_t)(goff+e*16), src + (size_t)e*16);
            }
        }
        CP_COMMIT();

#pragma unroll
        for (int s=0;s<3;++s)
#pragma unroll
            for (int j=0;j<4;++j)
#pragma unroll
                for (int c=0;c<4;++c) acc[s][j][c]=0.f;

        // ---- GEMM1': hE x W1b (K=128) ----
#pragma unroll
        for (int k=0;k<8;++k){
            uint32_t A[3][4], B[2][4];
#pragma unroll
            for (int s=0;s<3;++s) ldsm4(A[s], a_base + (uint32_t)(s*16*272 + k*32));
#pragma unroll
            for (int j2=0;j2<2;++j2) ldsm4t(B[j2], w1_base + (uint32_t)(k*16*272 + j2*32));
#pragma unroll
            for (int s=0;s<3;++s)
#pragma unroll
                for (int j2=0;j2<2;++j2){
                    mma16816(acc[s][2*j2],   A[s], B[j2]);
                    mma16816(acc[s][2*j2+1], A[s], B[j2]+2);
                }
        }
        CP_WAIT0();          // P(t) + F1 arrived (own copies)
        BAR_WG(wg+1);        // all copies visible

        // ---- epi1: M1 = gelu(acc + P) -> A buffer ----
#pragma unroll
        for (int s=0;s<3;++s){
            int r0 = s*16 + (lane>>2);
#pragma unroll
            for (int j=0;j<4;++j){
                int col = wn*32 + j*8 + 2*(lane&3);
                __nv_bfloat162 pa = *reinterpret_cast<__nv_bfloat162*>(sm + poff + r0*272 + col*2);
                __nv_bfloat162 pc = *reinterpret_cast<__nv_bfloat162*>(sm + poff + (r0+8)*272 + col*2);
                float x0=gelu_fast(acc[s][j][0]+__bfloat162float(pa.x));
                float x1=gelu_fast(acc[s][j][1]+__bfloat162float(pa.y));
                float x2=gelu_fast(acc[s][j][2]+__bfloat162float(pc.x));
                float x3=gelu_fast(acc[s][j][3]+__bfloat162float(pc.y));
                __nv_bfloat162 p0=__floats2bfloat162_rn(x0,x1), p1=__floats2bfloat162_rn(x2,x3);
                *reinterpret_cast<uint32_t*>(sm + aoff + r0*272 + col*2)     = *reinterpret_cast<uint32_t*>(&p0);
                *reinterpret_cast<uint32_t*>(sm + aoff + (r0+8)*272 + col*2) = *reinterpret_cast<uint32_t*>(&p1);
            }
        }
#pragma unroll
        for (int s=0;s<3;++s)
#pragma unroll
            for (int j=0;j<4;++j)
#pragma unroll
                for (int c=0;c<4;++c) acc[s][j][c]=0.f;
        BAR_WG(wg+1);   // M1 visible

        // ---- GEMM2: M1 (K=128) x W2 ----
#pragma unroll
        for (int k=0;k<8;++k){
            uint32_t A[3][4], B[2][4];
#pragma unroll
            for (int s=0;s<3;++s) ldsm4(A[s], a_base + (uint32_t)(s*16*272 + k*32));
#pragma unroll
            for (int j2=0;j2<2;++j2) ldsm4t(B[j2], w2_base + (uint32_t)(k*16*272 + j2*32));
#pragma unroll
            for (int s=0;s<3;++s)
#pragma unroll
                for (int j2=0;j2<2;++j2){
                    mma16816(acc[s][2*j2],   A[s], B[j2]);
                    mma16816(acc[s][2*j2+1], A[s], B[j2]+2);
                }
        }
        BAR_WG(wg+1);   // all warps done reading M1 (A buffer free)

        if (hn){
            // ---- convert staging rows[0:24) -> A; issue F2 rows[24:48) ----
#pragma unroll
            for (int q=0;q<6;++q){
                int e = wg_tid + 128*q;
                float4 v = *reinterpret_cast<const float4*>(sm+goff+e*16);
                __nv_bfloat162 p0=__floats2bfloat162_rn(v.x,v.y), p1=__floats2bfloat162_rn(v.z,v.w);
                uint2 pk; pk.x=*reinterpret_cast<uint32_t*>(&p0); pk.y=*reinterpret_cast<uint32_t*>(&p1);
                *reinterpret_cast<uint2*>(sm + aoff + (e>>5)*272 + (e&31)*8) = pk;
            }
            const char* src = reinterpret_cast<const char*>(hE) + ((size_t)(t+N_STREAMS)*ROWS_T + 24)*512;
#pragma unroll
            for (int q=0;q<6;++q){
                int e = wg_tid + 128*q;
                cpasync16(smb+(uint32_t)(goff+e*16), src + (size_t)e*16);
            }
            CP_COMMIT();
        }

        // ---- epi2: gelu(acc+b2)*mask, full-node column sums -> g_s2 (plain stores) ----
        float ra[4], rb[4];
#pragma unroll
        for (int j=0;j<4;++j){ ra[j]=0.f; rb[j]=0.f; }
#pragma unroll
        for (int s=0;s<3;++s){
            const float mka = msk[s*16 + (lane>>2)];
            const float mkb = msk[s*16 + (lane>>2) + 8];
#pragma unroll
            for (int j=0;j<4;++j){
                int c = wn*32 + j*8 + 2*(lane&3);
                float2 bb = *reinterpret_cast<float2*>(&b2s[c]);
                float v0 = gelu_fast(acc[s][j][0]+bb.x)*mka;
                float v1 = gelu_fast(acc[s][j][1]+bb.y)*mka;
                float v2 = gelu_fast(acc[s][j][2]+bb.x)*mkb;
                float v3 = gelu_fast(acc[s][j][3]+bb.y)*mkb;
                ra[j] += v0+v2;
                rb[j] += v1+v3;
            }
        }
#pragma unroll
        for (int j=0;j<4;++j){
            float s0=ra[j], s1=rb[j];
            s0 += __shfl_xor_sync(0xffffffffu,s0,4);
            s0 += __shfl_xor_sync(0xffffffffu,s0,8);
            s0 += __shfl_xor_sync(0xffffffffu,s0,16);
            s1 += __shfl_xor_sync(0xffffffffu,s1,4);
            s1 += __shfl_xor_sync(0xffffffffu,s1,8);
            s1 += __shfl_xor_sync(0xffffffffu,s1,16);
            if (lane<4){
                int col = wn*32 + j*8 + 2*lane;
                g_s2[(size_t)t*Hc + col]   = s0;
                g_s2[(size_t)t*Hc + col+1] = s1;
            }
        }

        // ---- drain F2; convert staging rows[24:48) -> A ----
        if (hn){
            CP_WAIT0();
#pragma unroll
            for (int q=0;q<6;++q){
                int e = wg_tid + 128*q;
                float4 v = *reinterpret_cast<const float4*>(sm+goff+e*16);
                __nv_bfloat162 p0=__floats2bfloat162_rn(v.x,v.y), p1=__floats2bfloat162_rn(v.z,v.w);
                uint2 pk; pk.x=*reinterpret_cast<uint32_t*>(&p0); pk.y=*reinterpret_cast<uint32_t*>(&p1);
                *reinterpret_cast<uint2*>(sm + aoff + (24 + (e>>5))*272 + (e&31)*8) = pk;
            }
        }

        BAR_WG(wg+1);
    }
}

// ---------------- fused node kernel: 512 threads, weight cp.async slot-pipelining ----------------
constexpr int NOFF_S2HI = 0;
constexpr int NOFF_S2LO = 17408;
constexpr int NOFF_HHI  = 34816;
constexpr int NOFF_HLO  = 52224;
constexpr int NOFF_W    = 69632;     // slots: +0 WinHi/W3hi, +34816 WinLo/W3lo, +69632 WoutHi, +104448 WoutLo
constexpr int NOFF_B3   = 208896;
constexpr int NOFF_BIN  = 209408;
constexpr int NOFF_BOUT = 211456;
constexpr int NOFF_MV   = 211968;
constexpr int NOFF_CNT  = 212224;
constexpr int NODE_SMEM = 212480;

__global__ __launch_bounds__(512,1)
void node_kernel(const float* __restrict__ hV, const float* __restrict__ maskV,
                 const float* __restrict__ b3, const float* __restrict__ b_in,
                 const float* __restrict__ b_out, float* __restrict__ out){
    extern __shared__ __align__(16) char sm[];
    const int tid=threadIdx.x, wid=tid>>5, lane=tid&31;
    const int wm=wid&3, wn=wid>>2;
    const int rowbase = blockIdx.x*64;
    const uint32_t smb=smem_u32(sm);
    float* b3s  = reinterpret_cast<float*>(sm+NOFF_B3);
    float* bins = reinterpret_cast<float*>(sm+NOFF_BIN);
    float* bouts= reinterpret_cast<float*>(sm+NOFF_BOUT);
    float* mvs  = reinterpret_cast<float*>(sm+NOFF_MV);
    float* cnts = reinterpret_cast<float*>(sm+NOFF_CNT);

    if (tid<128) b3s[tid]=b3[tid];
    for (int i=tid;i<FFc;i+=512) bins[i]=b_in[i];
    if (tid>=128 && tid<256) bouts[tid-128]=b_out[tid-128];
    if (tid<64){ mvs[tid]=maskV[rowbase+tid]; cnts[tid]=g_cnt[rowbase+tid]; }

    for (int e=tid;e<64*32;e+=512){
        int r=e>>5, q=e&31;
        float4 v = reinterpret_cast<const float4*>(g_s2 + (size_t)(rowbase+r)*Hc)[q];
        __nv_bfloat16 hx=__float2bfloat16(v.x),hy=__float2bfloat16(v.y),
                      hz=__float2bfloat16(v.z),hw=__float2bfloat16(v.w);
        __nv_bfloat162 ph0=__halves2bfloat162(hx,hy), ph1=__halves2bfloat162(hz,hw);
        __nv_bfloat162 pl0=__floats2bfloat162_rn(v.x-__bfloat162float(hx),v.y-__bfloat162float(hy));
        __nv_bfloat162 pl1=__floats2bfloat162_rn(v.z-__bfloat162float(hz),v.w-__bfloat162float(hw));
        uint2 uh; uh.x=*reinterpret_cast<uint32_t*>(&ph0); uh.y=*reinterpret_cast<uint32_t*>(&ph1);
        uint2 ul; ul.x=*reinterpret_cast<uint32_t*>(&pl0); ul.y=*reinterpret_cast<uint32_t*>(&pl1);
        *reinterpret_cast<uint2*>(sm + NOFF_S2HI + r*272 + q*8) = uh;
        *reinterpret_cast<uint2*>(sm + NOFF_S2LO + r*272 + q*8) = ul;
    }
    // W3 hi/lo into slots 0/1
    for (int i=tid;i<128*16;i+=512){
        int r=i>>4, q=i&15;
        *reinterpret_cast<uint4*>(sm+NOFF_W+r*272+q*16)       = *reinterpret_cast<const uint4*>(g_W3hi + r*Hc + q*8);
        *reinterpret_cast<uint4*>(sm+NOFF_W+34816+r*272+q*16) = *reinterpret_cast<const uint4*>(g_W3lo + r*Hc + q*8);
    }
    __syncthreads();

    const uint32_t a_row = (uint32_t)((wm*16 + (lane&15))*272 + (lane>>4)*16);
    const uint32_t b_row = (uint32_t)((lane&15)*272 + (wn*32 + (lane>>4)*8)*2);

    auto gemm3 = [&](float acc[4][4], uint32_t ahi, uint32_t alo, uint32_t bhi, uint32_t blo){
#pragma unroll
        for (int k=0;k<8;++k){
            uint32_t Ah[4], Al[4], Bh[2][4], Bl[2][4];
            ldsm4(Ah, ahi + (uint32_t)(k*32));
            ldsm4(Al, alo + (uint32_t)(k*32));
#pragma unroll
            for (int j2=0;j2<2;++j2){
                ldsm4t(Bh[j2], bhi + (uint32_t)(k*16*272 + j2*32));
                ldsm4t(Bl[j2], blo + (uint32_t)(k*16*272 + j2*32));
            }
#pragma unroll
            for (int j2=0;j2<2;++j2){
                mma16816(acc[2*j2],   Ah, Bh[j2]);
                mma16816(acc[2*j2+1], Ah, Bh[j2]+2);
                mma16816(acc[2*j2],   Ah, Bl[j2]);
                mma16816(acc[2*j2+1], Ah, Bl[j2]+2);
                mma16816(acc[2*j2],   Al, Bh[j2]);
                mma16816(acc[2*j2+1], Al, Bh[j2]+2);
            }
        }
    };

    // weight chunk prefetchers (cp.async, 16B granules; rows are 256B contiguous)
    auto fetch_win = [&](int cc){
#pragma unroll
        for (int q=0;q<4;++q){
            int u = tid + 512*q;          // 0..2047
            int r = u>>4, c16 = u&15;
            cpasync16(smb+NOFF_W + (uint32_t)(r*272 + c16*16),
                      reinterpret_cast<const char*>(g_WinHi) + ((size_t)r*FFc + cc*128 + c16*8)*2);
            cpasync16(smb+NOFF_W+34816 + (uint32_t)(r*272 + c16*16),
                      reinterpret_cast<const char*>(g_WinLo) + ((size_t)r*FFc + cc*128 + c16*8)*2);
        }
    };
    auto fetch_wout = [&](int cc){
#pragma unroll
        for (int q=0;q<4;++q){
            int u = tid + 512*q;
            int r = u>>4, c16 = u&15;
            cpasync16(smb+NOFF_W+69632 + (uint32_t)(r*272 + c16*16),
                      reinterpret_cast<const char*>(g_WoutHi) + (((size_t)(cc*128+r))*Hc + c16*8)*2);
            cpasync16(smb+NOFF_W+104448 + (uint32_t)(r*272 + c16*16),
                      reinterpret_cast<const char*>(g_WoutLo) + (((size_t)(cc*128+r))*Hc + c16*8)*2);
        }
    };

    // ---- stage0: h = hV + (S2@W3 + cnt*b3)/30 ----
    {
        float acc[4][4];
#pragma unroll
        for (int j=0;j<4;++j)
#pragma unroll
            for (int c=0;c<4;++c) acc[j][c]=0.f;
        gemm3(acc, smb+NOFF_S2HI+a_row, smb+NOFF_S2LO+a_row,
                   smb+NOFF_W+b_row,    smb+NOFF_W+34816+b_row);
        int r0 = wm*16 + (lane>>2);
#pragma unroll
        for (int j=0;j<4;++j){
            int c = wn*32 + j*8 + 2*(lane&3);
#pragma unroll
            for (int half=0; half<2; ++half){
                int r = r0 + half*8;
                size_t gi = (size_t)(rowbase+r)*Hc + c;
                float h0 = hV[gi]   + (acc[j][2*half]   + cnts[r]*b3s[c])  *INV_SCALE;
                float h1 = hV[gi+1] + (acc[j][2*half+1] + cnts[r]*b3s[c+1])*INV_SCALE;
                __nv_bfloat16 x0=__float2bfloat16(h0), x1=__float2bfloat16(h1);
                __nv_bfloat162 ph=__halves2bfloat162(x0,x1);
                __nv_bfloat162 pl=__floats2bfloat162_rn(h0-__bfloat162float(x0),h1-__bfloat162float(x1));
                *reinterpret_cast<uint32_t*>(sm+NOFF_HHI+r*272+c*2)=*reinterpret_cast<uint32_t*>(&ph);
                *reinterpret_cast<uint32_t*>(sm+NOFF_HLO+r*272+c*2)=*reinterpret_cast<uint32_t*>(&pl);
            }
        }
    }
    __syncthreads();     // all warps done with W3 (slots 0/1 free); H visible

    // prologue: prefetch chunk 0 weights (all 4 slots)
    fetch_win(0);
    fetch_wout(0);
    CP_COMMIT();

    float accO[4][4];
#pragma unroll
    for (int j=0;j<4;++j)
#pragma unroll
        for (int c=0;c<4;++c) accO[j][c]=0.f;

    for (int cc=0;cc<4;++cc){
        CP_WAIT0();
        __syncthreads();     // weights visible to all

        // GEMM1(cc): mid = gelu(h @ Win_cc + b_in_cc)  [reads slots 0/1]
        float accM[4][4];
#pragma unroll
        for (int j=0;j<4;++j)
#pragma unroll
            for (int c=0;c<4;++c) accM[j][c]=0.f;
        gemm3(accM, smb+NOFF_HHI+a_row, smb+NOFF_HLO+a_row,
                    smb+NOFF_W+b_row,   smb+NOFF_W+34816+b_row);
        {
            int r0 = wm*16 + (lane>>2);
#pragma unroll
            for (int j=0;j<4;++j){
                int c = wn*32 + j*8 + 2*(lane&3);
#pragma unroll
                for (int half=0; half<2; ++half){
                    int r = r0 + half*8;
                    float v0 = gelu_erf_f(accM[j][2*half]   + bins[cc*128+c]);
                    float v1 = gelu_erf_f(accM[j][2*half+1] + bins[cc*128+c+1]);
                    __nv_bfloat16 x0=__float2bfloat16(v0), x1=__float2bfloat16(v1);
                    __nv_bfloat162 ph=__halves2bfloat162(x0,x1);
                    __nv_bfloat162 pl=__floats2bfloat162_rn(v0-__bfloat162float(x0),v1-__bfloat162float(x1));
                    *reinterpret_cast<uint32_t*>(sm+NOFF_S2HI+r*272+c*2)=*reinterpret_cast<uint32_t*>(&ph);
                    *reinterpret_cast<uint32_t*>(sm+NOFF_S2LO+r*272+c*2)=*reinterpret_cast<uint32_t*>(&pl);
                }
            }
        }
        __syncthreads();     // mid visible; all warps done with Win slots

        if (cc<3){ fetch_win(cc+1); CP_COMMIT(); }   // overlaps with GEMM2

        // GEMM2(cc): accO += mid @ Wout_cc  [reads slots 2/3]
        gemm3(accO, smb+NOFF_S2HI+a_row, smb+NOFF_S2LO+a_row,
                    smb+NOFF_W+69632+b_row, smb+NOFF_W+104448+b_row);
        __syncthreads();     // all warps done with Wout slots + mid

        if (cc<3){ fetch_wout(cc+1); CP_COMMIT(); }  // overlaps with next GEMM1 (after wait)
    }

    {
        int r0 = wm*16 + (lane>>2);
#pragma unroll
        for (int j=0;j<4;++j){
            int c = wn*32 + j*8 + 2*(lane&3);
#pragma unroll
            for (int half=0; half<2; ++half){
                int r = r0 + half*8;
                size_t gi = (size_t)(rowbase+r)*Hc + c;
                __nv_bfloat162 hh = *reinterpret_cast<__nv_bfloat162*>(sm+NOFF_HHI+r*272+c*2);
                __nv_bfloat162 hl = *reinterpret_cast<__nv_bfloat162*>(sm+NOFF_HLO+r*272+c*2);
                float h0 = __bfloat162float(hh.x)+__bfloat162float(hl.x);
                float h1 = __bfloat162float(hh.y)+__bfloat162float(hl.y);
                float mv = mvs[r];
                out[gi]   = (h0 + accO[j][2*half]   + bouts[c])  * mv;
                out[gi+1] = (h1 + accO[j][2*half+1] + bouts[c+1])* mv;
            }
        }
    }
}

// ---------------- launch ----------------
extern "C" void kernel_launch(void* const* d_in, const int* in_sizes, int n_in,
                              void* d_out, int out_size){
    (void)in_sizes; (void)n_in; (void)out_size;
    const float* hV   =(const float*)d_in[0];
    const float* hE   =(const float*)d_in[1];
    const int*   eidx =(const int*)d_in[2];
    const float* maskV=(const float*)d_in[3];
    const float* mAtt =(const float*)d_in[4];
    const float* W1   =(const float*)d_in[5];
    const float* b1   =(const float*)d_in[6];
    const float* W2   =(const float*)d_in[7];
    const float* b2   =(const float*)d_in[8];
    const float* W3   =(const float*)d_in[9];
    const float* b3   =(const float*)d_in[10];
    const float* Win  =(const float*)d_in[11];
    const float* binp =(const float*)d_in[12];
    const float* Wout =(const float*)d_in[13];
    const float* boutp=(const float*)d_in[14];
    float* out=(float*)d_out;

    cudaFuncSetAttribute(setup_kernel, cudaFuncAttributeMaxDynamicSharedMemorySize, P1_SMEM);
    cudaFuncSetAttribute(edge_mlp_mma, cudaFuncAttributeMaxDynamicSharedMemorySize, EDGE_SMEM);
    cudaFuncSetAttribute(node_kernel, cudaFuncAttributeMaxDynamicSharedMemorySize, NODE_SMEM);

    setup_kernel<<<SETUP_GRID, 256, P1_SMEM>>>(hV, W1, b1, W3, Win, Wout, mAtt);
    edge_mlp_mma<<<148, 512, EDGE_SMEM>>>(hE, eidx, mAtt, W1, b2, W2);
    node_kernel<<<NODES/64, 512, NODE_SMEM>>>(hV, maskV, b3, binp, boutp, out);
}

// round 17
// speedup vs baseline: 1.6178x; 1.0173x over previous
#include <cuda_runtime.h>
#include <cuda_bf16.h>
#include <cstdint>

constexpr int Bc=4, Nn=2048, Kc=48, Hc=128, FFc=512;
constexpr int NODES = Bc*Nn;                 // 8192
constexpr int ROWS_T = 48;                   // edge tile rows = 1 node
constexpr int N_TILES = NODES;               // 8192
constexpr int N_STREAMS = 148*4;             // 592
constexpr float INV_SCALE = 1.0f/30.0f;

__device__ __nv_bfloat16 g_W3hi[Hc*Hc], g_W3lo[Hc*Hc];
__device__ __nv_bfloat16 g_WinHi[Hc*FFc], g_WinLo[Hc*FFc];
__device__ __nv_bfloat16 g_WoutHi[FFc*Hc], g_WoutLo[FFc*Hc];
__device__ __nv_bfloat16 g_P[NODES*Hc];      // hV @ W1a + b1 (bf16)
__device__ float g_s2[NODES*Hc];             // fully written by edge (no atomics)
__device__ float g_cnt[NODES];

// ---------------- low-level helpers ----------------
__device__ __forceinline__ uint32_t smem_u32(const void* p){
    uint32_t a; asm("{ .reg .u64 t; cvta.to.shared.u64 t, %1; cvt.u32.u64 %0, t; }":"=r"(a):"l"(p)); return a;
}
__device__ __forceinline__ void ldsm4(uint32_t* r, uint32_t addr){
    asm volatile("ldmatrix.sync.aligned.m8n8.x4.shared.b16 {%0,%1,%2,%3},[%4];"
        :"=r"(r[0]),"=r"(r[1]),"=r"(r[2]),"=r"(r[3]):"r"(addr));
}
__device__ __forceinline__ void ldsm4t(uint32_t* r, uint32_t addr){
    asm volatile("ldmatrix.sync.aligned.m8n8.x4.trans.shared.b16 {%0,%1,%2,%3},[%4];"
        :"=r"(r[0]),"=r"(r[1]),"=r"(r[2]),"=r"(r[3]):"r"(addr));
}
__device__ __forceinline__ void mma16816(float* d, const uint32_t* a, const uint32_t* b){
    asm volatile("mma.sync.aligned.m16n8k16.row.col.f32.bf16.bf16.f32 "
        "{%0,%1,%2,%3},{%4,%5,%6,%7},{%8,%9},{%0,%1,%2,%3};"
        :"+f"(d[0]),"+f"(d[1]),"+f"(d[2]),"+f"(d[3])
        :"r"(a[0]),"r"(a[1]),"r"(a[2]),"r"(a[3]),"r"(b[0]),"r"(b[1]));
}
__device__ __forceinline__ void cpasync16(uint32_t dst, const void* src){
    asm volatile("cp.async.cg.shared.global [%0],[%1],16;"::"r"(dst),"l"(src):"memory");
}
#define CP_COMMIT() asm volatile("cp.async.commit_group;":::"memory")
#define CP_WAIT0()  asm volatile("cp.async.wait_group 0;":::"memory")
#define CP_WAIT1()  asm volatile("cp.async.wait_group 1;":::"memory")
#define BAR_WG(id) asm volatile("bar.sync %0, %1;"::"r"((id)),"r"(128):"memory")

__device__ __forceinline__ float gelu_fast(float x){
    float t1 = x*x;
    float y  = x*__fmaf_rn(0.0356774081f, t1, 0.7978845608f);
    float t; asm("tanh.approx.f32 %0, %1;":"=f"(t):"f"(y));
    float h = 0.5f*x;
    return __fmaf_rn(h, t, h);
}
__device__ __forceinline__ float gelu_erf_f(float x){ return x*normcdff(x); }

// ---------------- pre1: P = hV @ W1[0:128,:] + b1 (bf16) + cnt, 32 rows/block ----------------
constexpr int P1_A = 0;            // 32*272 = 8704
constexpr int P1_W = 8704;         // 34816
constexpr int P1_B = 43520;        // 512
constexpr int P1_SMEM = 44032;

__global__ __launch_bounds__(256,1)
void pre1_kernel(const float* __restrict__ hV,
                 const float* __restrict__ W1, const float* __restrict__ b1,
                 const float* __restrict__ mAtt){
    extern __shared__ __align__(16) char sm[];
    const int tid=threadIdx.x;
    const int wid=tid>>5, lane=tid&31;
    const int wm=wid&1, wn=wid>>1;      // 2 M-tiles(16) x 4 N-tiles(32)
    const int rowbase = blockIdx.x*32;
    const uint32_t smb=smem_u32(sm);
    float* b1s = reinterpret_cast<float*>(sm+P1_B);

    if (tid<128) b1s[tid]=b1[tid];
    if (tid<32){
        float s=0.f;
        const float* mrow = mAtt + (size_t)(rowbase+tid)*Kc;
#pragma unroll 12
        for (int k=0;k<Kc;++k) s+=mrow[k];
        g_cnt[rowbase+tid]=s;
    }
    for (int i=tid;i<128*128;i+=256){
        int k=i>>7, n=i&127;
        *reinterpret_cast<__nv_bfloat16*>(sm+P1_W+k*272+n*2) = __float2bfloat16(W1[k*128+n]);
    }
    for (int e=tid;e<32*32;e+=256){
        int r=e>>5, q=e&31;
        float4 v = reinterpret_cast<const float4*>(hV + (size_t)(rowbase+r)*Hc)[q];
        __nv_bfloat162 p0=__floats2bfloat162_rn(v.x,v.y), p1=__floats2bfloat162_rn(v.z,v.w);
        uint2 pk; pk.x=*reinterpret_cast<uint32_t*>(&p0); pk.y=*reinterpret_cast<uint32_t*>(&p1);
        *reinterpret_cast<uint2*>(sm + P1_A + r*272 + q*8) = pk;
    }
    __syncthreads();

    const uint32_t a_row = smb + P1_A + (uint32_t)((wm*16 + (lane&15))*272 + (lane>>4)*16);
    const uint32_t b_row = smb + P1_W + (uint32_t)((lane&15)*272 + (wn*32 + (lane>>4)*8)*2);

    float acc[4][4];
#pragma unroll
    for (int j=0;j<4;++j)
#pragma unroll
        for (int c=0;c<4;++c) acc[j][c]=0.f;
#pragma unroll
    for (int k=0;k<8;++k){
        uint32_t A[4], B[2][4];
        ldsm4(A, a_row + (uint32_t)(k*32));
#pragma unroll
        for (int j2=0;j2<2;++j2) ldsm4t(B[j2], b_row + (uint32_t)(k*16*272 + j2*32));
#pragma unroll
        for (int j2=0;j2<2;++j2){
            mma16816(acc[2*j2],   A, B[j2]);
            mma16816(acc[2*j2+1], A, B[j2]+2);
        }
    }
    {
        int r0 = wm*16 + (lane>>2);
#pragma unroll
        for (int j=0;j<4;++j){
            int c = wn*32 + j*8 + 2*(lane&3);
#pragma unroll
            for (int half=0; half<2; ++half){
                int r = r0 + half*8;
                float v0 = acc[j][2*half]   + b1s[c];
                float v1 = acc[j][2*half+1] + b1s[c+1];
                __nv_bfloat162 p=__floats2bfloat162_rn(v0,v1);
                *reinterpret_cast<uint32_t*>(&g_P[(size_t)(rowbase+r)*Hc + c]) = *reinterpret_cast<uint32_t*>(&p);
            }
        }
    }
}

// ---------------- edge MLP: 4 WGs x 48-row (1-node) tiles + weight-split prologue ----------------
constexpr int WG_SZ   = 38400;
constexpr int OFF_W1B = 153600;     // 34816
constexpr int OFF_W2  = 188416;     // 34816
constexpr int OFF_B2  = 223232;     // 512
constexpr int OFF_MSK = 223744;     // 4 x 256
constexpr int EDGE_SMEM = 224768;

__global__ __launch_bounds__(512,1)
void edge_mlp_mma(const float* __restrict__ hE,
                  const int* __restrict__ eidx, const float* __restrict__ mAtt,
                  const float* __restrict__ W1, const float* __restrict__ b2,
                  const float* __restrict__ W2,
                  const float* __restrict__ W3, const float* __restrict__ Win,
                  const float* __restrict__ Wout){
    extern __shared__ __align__(16) char sm[];
    const int tid=threadIdx.x, wid=tid>>5, lane=tid&31;
    const int wg=wid>>2, wn=wid&3;     // 4 WGs; warp tile M=48 x N=32
    const int wg_tid=tid&127;
    const uint32_t smb=smem_u32(sm);
    float* b2s=reinterpret_cast<float*>(sm+OFF_B2);
    float* msk=reinterpret_cast<float*>(sm+OFF_MSK+wg*256);
    const int aoff = wg*WG_SZ;
    const int poff = aoff + 13056;
    const int goff = aoff + 26112;

    // one-time weight split for the node kernel (each thread <=1 element)
    {
        int i = blockIdx.x*512 + tid;
        if (i < Hc*FFc){
            float v=Win[i]; __nv_bfloat16 h=__float2bfloat16(v);
            g_WinHi[i]=h; g_WinLo[i]=__float2bfloat16(v-__bfloat162float(h));
            v=Wout[i]; h=__float2bfloat16(v);
            g_WoutHi[i]=h; g_WoutLo[i]=__float2bfloat16(v-__bfloat162float(h));
        }
        if (i < Hc*Hc){
            float v=W3[i]; __nv_bfloat16 h=__float2bfloat16(v);
            g_W3hi[i]=h; g_W3lo[i]=__float2bfloat16(v-__bfloat162float(h));
        }
    }

    for (int i=tid;i<128*128;i+=512){
        int k=i>>7, n=i&127;
        *reinterpret_cast<__nv_bfloat16*>(sm+OFF_W1B+k*272+n*2) = __float2bfloat16(W1[(128+k)*128+n]);
        *reinterpret_cast<__nv_bfloat16*>(sm+OFF_W2 +k*272+n*2) = __float2bfloat16(W2[k*128+n]);
    }
    if (tid<128) b2s[tid]=b2[tid];
    __syncthreads();

    const uint32_t a_base  = smb + (uint32_t)aoff + (uint32_t)((lane&15)*272 + (lane>>4)*16);
    const uint32_t w1_base = smb + OFF_W1B + (uint32_t)((lane&15)*272 + (wn*32 + (lane>>4)*8)*2);
    const uint32_t w2_base = smb + OFF_W2  + (uint32_t)((lane&15)*272 + (wn*32 + (lane>>4)*8)*2);

    float acc[3][4][4];
    const int t0 = blockIdx.x*4+wg;
    const int prow = wg_tid>>1, phalf = wg_tid&1;

    // ---- prologue: hE(t0) -> A (bf16) in two half-tile staging passes ----
#pragma unroll
    for (int h=0;h<2;++h){
        const char* src = reinterpret_cast<const char*>(hE) + ((size_t)t0*ROWS_T + h*24)*512;
#pragma unroll
        for (int q=0;q<6;++q){
            int e = wg_tid + 128*q;
            cpasync16(smb+(uint32_t)(goff+e*16), src + (size_t)e*16);
        }
        CP_COMMIT(); CP_WAIT0();
#pragma unroll
        for (int q=0;q<6;++q){
            int e = wg_tid + 128*q;
            float4 v = *reinterpret_cast<const float4*>(sm+goff+e*16);
            __nv_bfloat162 p0=__floats2bfloat162_rn(v.x,v.y), p1=__floats2bfloat162_rn(v.z,v.w);
            uint2 pk; pk.x=*reinterpret_cast<uint32_t*>(&p0); pk.y=*reinterpret_cast<uint32_t*>(&p1);
            *reinterpret_cast<uint2*>(sm + aoff + (h*24 + (e>>5))*272 + (e&31)*8) = pk;
        }
    }
    BAR_WG(wg+1);

    for (int t = t0; t < N_TILES; t += N_STREAMS){
        const bool hn = (t+N_STREAMS) < N_TILES;

        // ---- P(t) gather (threads 0-95) + mask ----
        if (wg_tid < 96){
            const int nb = eidx[t*Kc + prow];
            const char* sp = reinterpret_cast<const char*>(g_P)
                           + (((size_t)(t>>11)<<11) + nb)*256 + phalf*128;
            uint32_t dP = smb + (uint32_t)(poff + prow*272 + phalf*128);
#pragma unroll
            for (int q=0;q<8;++q) cpasync16(dP+q*16, sp+q*16);
        }
        if (wg_tid<48) msk[wg_tid] = mAtt[t*Kc + wg_tid];
        CP_COMMIT();
        // ---- F1: next tile's hE rows [0,24) -> staging ----
        if (hn){
            const char* src = reinterpret_cast<const char*>(hE) + (size_t)(t+N_STREAMS)*ROWS_T*512;
#pragma unroll
            for (int q=0;q<6;++q){
                int e = wg_tid + 128*q;
                cpasync16(smb+(uint32_t)(goff+e*16), src + (size_t)e*16);
            }
        }
        CP_COMMIT();

#pragma unroll
        for (int s=0;s<3;++s)
#pragma unroll
            for (int j=0;j<4;++j)
#pragma unroll
                for (int c=0;c<4;++c) acc[s][j][c]=0.f;

        // ---- GEMM1': hE x W1b (K=128) ----
#pragma unroll
        for (int k=0;k<8;++k){
            uint32_t A[3][4], B[2][4];
#pragma unroll
            for (int s=0;s<3;++s) ldsm4(A[s], a_base + (uint32_t)(s*16*272 + k*32));
#pragma unroll
            for (int j2=0;j2<2;++j2) ldsm4t(B[j2], w1_base + (uint32_t)(k*16*272 + j2*32));
#pragma unroll
            for (int s=0;s<3;++s)
#pragma unroll
                for (int j2=0;j2<2;++j2){
                    mma16816(acc[s][2*j2],   A[s], B[j2]);
                    mma16816(acc[s][2*j2+1], A[s], B[j2]+2);
                }
        }
        CP_WAIT0();          // P(t) + F1 arrived (own copies)
        BAR_WG(wg+1);        // all copies visible

        // ---- epi1: M1 = gelu(acc + P) -> A buffer ----
#pragma unroll
        for (int s=0;s<3;++s){
            int r0 = s*16 + (lane>>2);
#pragma unroll
            for (int j=0;j<4;++j){
                int col = wn*32 + j*8 + 2*(lane&3);
                __nv_bfloat162 pa = *reinterpret_cast<__nv_bfloat162*>(sm + poff + r0*272 + col*2);
                __nv_bfloat162 pc = *reinterpret_cast<__nv_bfloat162*>(sm + poff + (r0+8)*272 + col*2);
                float x0=gelu_fast(acc[s][j][0]+__bfloat162float(pa.x));
                float x1=gelu_fast(acc[s][j][1]+__bfloat162float(pa.y));
                float x2=gelu_fast(acc[s][j][2]+__bfloat162float(pc.x));
                float x3=gelu_fast(acc[s][j][3]+__bfloat162float(pc.y));
                __nv_bfloat162 p0=__floats2bfloat162_rn(x0,x1), p1=__floats2bfloat162_rn(x2,x3);
                *reinterpret_cast<uint32_t*>(sm + aoff + r0*272 + col*2)     = *reinterpret_cast<uint32_t*>(&p0);
                *reinterpret_cast<uint32_t*>(sm + aoff + (r0+8)*272 + col*2) = *reinterpret_cast<uint32_t*>(&p1);
            }
        }
#pragma unroll
        for (int s=0;s<3;++s)
#pragma unroll
            for (int j=0;j<4;++j)
#pragma unroll
                for (int c=0;c<4;++c) acc[s][j][c]=0.f;
        BAR_WG(wg+1);   // M1 visible

        // ---- GEMM2: M1 (K=128) x W2 ----
#pragma unroll
        for (int k=0;k<8;++k){
            uint32_t A[3][4], B[2][4];
#pragma unroll
            for (int s=0;s<3;++s) ldsm4(A[s], a_base + (uint32_t)(s*16*272 + k*32));
#pragma unroll
            for (int j2=0;j2<2;++j2) ldsm4t(B[j2], w2_base + (uint32_t)(k*16*272 + j2*32));
#pragma unroll
            for (int s=0;s<3;++s)
#pragma unroll
                for (int j2=0;j2<2;++j2){
                    mma16816(acc[s][2*j2],   A[s], B[j2]);
                    mma16816(acc[s][2*j2+1], A[s], B[j2]+2);
                }
        }
        BAR_WG(wg+1);   // all warps done reading M1 (A buffer free)

        if (hn){
            // ---- convert staging rows[0:24) -> A; issue F2 rows[24:48) ----
#pragma unroll
            for (int q=0;q<6;++q){
                int e = wg_tid + 128*q;
                float4 v = *reinterpret_cast<const float4*>(sm+goff+e*16);
                __nv_bfloat162 p0=__floats2bfloat162_rn(v.x,v.y), p1=__floats2bfloat162_rn(v.z,v.w);
                uint2 pk; pk.x=*reinterpret_cast<uint32_t*>(&p0); pk.y=*reinterpret_cast<uint32_t*>(&p1);
                *reinterpret_cast<uint2*>(sm + aoff + (e>>5)*272 + (e&31)*8) = pk;
            }
            const char* src = reinterpret_cast<const char*>(hE) + ((size_t)(t+N_STREAMS)*ROWS_T + 24)*512;
#pragma unroll
            for (int q=0;q<6;++q){
                int e = wg_tid + 128*q;
                cpasync16(smb+(uint32_t)(goff+e*16), src + (size_t)e*16);
            }
            CP_COMMIT();
        }

        // ---- epi2: gelu(acc+b2)*mask, full-node column sums -> g_s2 ----
        float ra[4], rb[4];
#pragma unroll
        for (int j=0;j<4;++j){ ra[j]=0.f; rb[j]=0.f; }
#pragma unroll
        for (int s=0;s<3;++s){
            const float mka = msk[s*16 + (lane>>2)];
            const float mkb = msk[s*16 + (lane>>2) + 8];
#pragma unroll
            for (int j=0;j<4;++j){
                int c = wn*32 + j*8 + 2*(lane&3);
                float2 bb = *reinterpret_cast<float2*>(&b2s[c]);
                float v0 = gelu_fast(acc[s][j][0]+bb.x)*mka;
                float v1 = gelu_fast(acc[s][j][1]+bb.y)*mka;
                float v2 = gelu_fast(acc[s][j][2]+bb.x)*mkb;
                float v3 = gelu_fast(acc[s][j][3]+bb.y)*mkb;
                ra[j] += v0+v2;
                rb[j] += v1+v3;
            }
        }
#pragma unroll
        for (int j=0;j<4;++j){
            float s0=ra[j], s1=rb[j];
            s0 += __shfl_xor_sync(0xffffffffu,s0,4);
            s0 += __shfl_xor_sync(0xffffffffu,s0,8);
            s0 += __shfl_xor_sync(0xffffffffu,s0,16);
            s1 += __shfl_xor_sync(0xffffffffu,s1,4);
            s1 += __shfl_xor_sync(0xffffffffu,s1,8);
            s1 += __shfl_xor_sync(0xffffffffu,s1,16);
            if (lane<4){
                int col = wn*32 + j*8 + 2*lane;
                g_s2[(size_t)t*Hc + col]   = s0;
                g_s2[(size_t)t*Hc + col+1] = s1;
            }
        }

        // ---- drain F2; convert staging rows[24:48) -> A ----
        if (hn){
            CP_WAIT0();
#pragma unroll
            for (int q=0;q<6;++q){
                int e = wg_tid + 128*q;
                float4 v = *reinterpret_cast<const float4*>(sm+goff+e*16);
                __nv_bfloat162 p0=__floats2bfloat162_rn(v.x,v.y), p1=__floats2bfloat162_rn(v.z,v.w);
                uint2 pk; pk.x=*reinterpret_cast<uint32_t*>(&p0); pk.y=*reinterpret_cast<uint32_t*>(&p1);
                *reinterpret_cast<uint2*>(sm + aoff + (24 + (e>>5))*272 + (e&31)*8) = pk;
            }
        }

        BAR_WG(wg+1);
    }
}

// ---------------- fused node kernel: overlapped weight slot-pipelining ----------------
constexpr int NOFF_S2HI = 0;
constexpr int NOFF_S2LO = 17408;
constexpr int NOFF_HHI  = 34816;
constexpr int NOFF_HLO  = 52224;
constexpr int NOFF_W    = 69632;     // slots: +0 WinHi, +34816 WinLo, +69632 WoutHi/W3hi, +104448 WoutLo/W3lo
constexpr int NOFF_B3   = 208896;
constexpr int NOFF_BIN  = 209408;
constexpr int NOFF_BOUT = 211456;
constexpr int NOFF_MV   = 211968;
constexpr int NOFF_CNT  = 212224;
constexpr int NODE_SMEM = 212480;

__global__ __launch_bounds__(512,1)
void node_kernel(const float* __restrict__ hV, const float* __restrict__ maskV,
                 const float* __restrict__ b3, const float* __restrict__ b_in,
                 const float* __restrict__ b_out, float* __restrict__ out){
    extern __shared__ __align__(16) char sm[];
    const int tid=threadIdx.x, wid=tid>>5, lane=tid&31;
    const int wm=wid&3, wn=wid>>2;
    const int rowbase = blockIdx.x*64;
    const uint32_t smb=smem_u32(sm);
    float* b3s  = reinterpret_cast<float*>(sm+NOFF_B3);
    float* bins = reinterpret_cast<float*>(sm+NOFF_BIN);
    float* bouts= reinterpret_cast<float*>(sm+NOFF_BOUT);
    float* mvs  = reinterpret_cast<float*>(sm+NOFF_MV);
    float* cnts = reinterpret_cast<float*>(sm+NOFF_CNT);

    // weight chunk prefetchers (cp.async; rows are 256B contiguous)
    auto fetch_win = [&](int cc){
#pragma unroll
        for (int q=0;q<4;++q){
            int u = tid + 512*q;
            int r = u>>4, c16 = u&15;
            cpasync16(smb+NOFF_W + (uint32_t)(r*272 + c16*16),
                      reinterpret_cast<const char*>(g_WinHi) + ((size_t)r*FFc + cc*128 + c16*8)*2);
            cpasync16(smb+NOFF_W+34816 + (uint32_t)(r*272 + c16*16),
                      reinterpret_cast<const char*>(g_WinLo) + ((size_t)r*FFc + cc*128 + c16*8)*2);
        }
    };
    auto fetch_wout = [&](int cc){
#pragma unroll
        for (int q=0;q<4;++q){
            int u = tid + 512*q;
            int r = u>>4, c16 = u&15;
            cpasync16(smb+NOFF_W+69632 + (uint32_t)(r*272 + c16*16),
                      reinterpret_cast<const char*>(g_WoutHi) + (((size_t)(cc*128+r))*Hc + c16*8)*2);
            cpasync16(smb+NOFF_W+104448 + (uint32_t)(r*272 + c16*16),
                      reinterpret_cast<const char*>(g_WoutLo) + (((size_t)(cc*128+r))*Hc + c16*8)*2);
        }
    };

    // fetch Win(0) into slots 0/1 at kernel entry (overlaps everything below)
    fetch_win(0);
    CP_COMMIT();

    if (tid<128) b3s[tid]=b3[tid];
    for (int i=tid;i<FFc;i+=512) bins[i]=b_in[i];
    if (tid>=128 && tid<256) bouts[tid-128]=b_out[tid-128];
    if (tid<64){ mvs[tid]=maskV[rowbase+tid]; cnts[tid]=g_cnt[rowbase+tid]; }

    for (int e=tid;e<64*32;e+=512){
        int r=e>>5, q=e&31;
        float4 v = reinterpret_cast<const float4*>(g_s2 + (size_t)(rowbase+r)*Hc)[q];
        __nv_bfloat16 hx=__float2bfloat16(v.x),hy=__float2bfloat16(v.y),
                      hz=__float2bfloat16(v.z),hw=__float2bfloat16(v.w);
        __nv_bfloat162 ph0=__halves2bfloat162(hx,hy), ph1=__halves2bfloat162(hz,hw);
        __nv_bfloat162 pl0=__floats2bfloat162_rn(v.x-__bfloat162float(hx),v.y-__bfloat162float(hy));
        __nv_bfloat162 pl1=__floats2bfloat162_rn(v.z-__bfloat162float(hz),v.w-__bfloat162float(hw));
        uint2 uh; uh.x=*reinterpret_cast<uint32_t*>(&ph0); uh.y=*reinterpret_cast<uint32_t*>(&ph1);
        uint2 ul; ul.x=*reinterpret_cast<uint32_t*>(&pl0); ul.y=*reinterpret_cast<uint32_t*>(&pl1);
        *reinterpret_cast<uint2*>(sm + NOFF_S2HI + r*272 + q*8) = uh;
        *reinterpret_cast<uint2*>(sm + NOFF_S2LO + r*272 + q*8) = ul;
    }
    // W3 hi/lo into slots 2/3
    for (int i=tid;i<128*16;i+=512){
        int r=i>>4, q=i&15;
        *reinterpret_cast<uint4*>(sm+NOFF_W+69632+r*272+q*16)  = *reinterpret_cast<const uint4*>(g_W3hi + r*Hc + q*8);
        *reinterpret_cast<uint4*>(sm+NOFF_W+104448+r*272+q*16) = *reinterpret_cast<const uint4*>(g_W3lo + r*Hc + q*8);
    }
    __syncthreads();

    const uint32_t a_row = (uint32_t)((wm*16 + (lane&15))*272 + (lane>>4)*16);
    const uint32_t b_row = (uint32_t)((lane&15)*272 + (wn*32 + (lane>>4)*8)*2);

    auto gemm3 = [&](float acc[4][4], uint32_t ahi, uint32_t alo, uint32_t bhi, uint32_t blo){
#pragma unroll
        for (int k=0;k<8;++k){
            uint32_t Ah[4], Al[4], Bh[2][4], Bl[2][4];
            ldsm4(Ah, ahi + (uint32_t)(k*32));
            ldsm4(Al, alo + (uint32_t)(k*32));
#pragma unroll
            for (int j2=0;j2<2;++j2){
                ldsm4t(Bh[j2], bhi + (uint32_t)(k*16*272 + j2*32));
                ldsm4t(Bl[j2], blo + (uint32_t)(k*16*272 + j2*32));
            }
#pragma unroll
            for (int j2=0;j2<2;++j2){
                mma16816(acc[2*j2],   Ah, Bh[j2]);
                mma16816(acc[2*j2+1], Ah, Bh[j2]+2);
                mma16816(acc[2*j2],   Ah, Bl[j2]);
                mma16816(acc[2*j2+1], Ah, Bl[j2]+2);
                mma16816(acc[2*j2],   Al, Bh[j2]);
                mma16816(acc[2*j2+1], Al, Bh[j2]+2);
            }
        }
    };

    // ---- stage0: h = hV + (S2@W3 + cnt*b3)/30  [W3 in slots 2/3] ----
    {
        float acc[4][4];
#pragma unroll
        for (int j=0;j<4;++j)
#pragma unroll
            for (int c=0;c<4;++c) acc[j][c]=0.f;
        gemm3(acc, smb+NOFF_S2HI+a_row, smb+NOFF_S2LO+a_row,
                   smb+NOFF_W+69632+b_row, smb+NOFF_W+104448+b_row);
        int r0 = wm*16 + (lane>>2);
#pragma unroll
        for (int j=0;j<4;++j){
            int c = wn*32 + j*8 + 2*(lane&3);
#pragma unroll
            for (int half=0; half<2; ++half){
                int r = r0 + half*8;
                size_t gi = (size_t)(rowbase+r)*Hc + c;
                float h0 = hV[gi]   + (acc[j][2*half]   + cnts[r]*b3s[c])  *INV_SCALE;
                float h1 = hV[gi+1] + (acc[j][2*half+1] + cnts[r]*b3s[c+1])*INV_SCALE;
                __nv_bfloat16 x0=__float2bfloat16(h0), x1=__float2bfloat16(h1);
                __nv_bfloat162 ph=__halves2bfloat162(x0,x1);
                __nv_bfloat162 pl=__floats2bfloat162_rn(h0-__bfloat162float(x0),h1-__bfloat162float(x1));
                *reinterpret_cast<uint32_t*>(sm+NOFF_HHI+r*272+c*2)=*reinterpret_cast<uint32_t*>(&ph);
                *reinterpret_cast<uint32_t*>(sm+NOFF_HLO+r*272+c*2)=*reinterpret_cast<uint32_t*>(&pl);
            }
        }
    }
    __syncthreads();     // all warps done with W3 (slots 2/3 free); H visible

    fetch_wout(0);       // overlaps GEMM1(0)
    CP_COMMIT();

    float accO[4][4];
#pragma unroll
    for (int j=0;j<4;++j)
#pragma unroll
        for (int c=0;c<4;++c) accO[j][c]=0.f;

    for (int cc=0;cc<4;++cc){
        CP_WAIT1();          // Win(cc) done; Wout(cc) may still fly
        __syncthreads();

        // GEMM1(cc): mid = gelu(h @ Win_cc + b_in_cc)  [slots 0/1]
        float accM[4][4];
#pragma unroll
        for (int j=0;j<4;++j)
#pragma unroll
            for (int c=0;c<4;++c) accM[j][c]=0.f;
        gemm3(accM, smb+NOFF_HHI+a_row, smb+NOFF_HLO+a_row,
                    smb+NOFF_W+b_row,   smb+NOFF_W+34816+b_row);
        {
            int r0 = wm*16 + (lane>>2);
#pragma unroll
            for (int j=0;j<4;++j){
                int c = wn*32 + j*8 + 2*(lane&3);
#pragma unroll
                for (int half=0; half<2; ++half){
                    int r = r0 + half*8;
                    float v0 = gelu_erf_f(accM[j][2*half]   + bins[cc*128+c]);
                    float v1 = gelu_erf_f(accM[j][2*half+1] + bins[cc*128+c+1]);
                    __nv_bfloat16 x0=__float2bfloat16(v0), x1=__float2bfloat16(v1);
                    __nv_bfloat162 ph=__halves2bfloat162(x0,x1);
                    __nv_bfloat162 pl=__floats2bfloat162_rn(v0-__bfloat162float(x0),v1-__bfloat162float(x1));
                    *reinterpret_cast<uint32_t*>(sm+NOFF_S2HI+r*272+c*2)=*reinterpret_cast<uint32_t*>(&ph);
                    *reinterpret_cast<uint32_t*>(sm+NOFF_S2LO+r*272+c*2)=*reinterpret_cast<uint32_t*>(&pl);
                }
            }
        }
        __syncthreads();     // mid visible; Win slots free

        if (cc<3){ fetch_win(cc+1); CP_COMMIT(); }   // overlaps GEMM2(cc)

        if (cc<3) CP_WAIT1(); else CP_WAIT0();       // Wout(cc) done
        __syncthreads();

        // GEMM2(cc): accO += mid @ Wout_cc  [slots 2/3]
        gemm3(accO, smb+NOFF_S2HI+a_row, smb+NOFF_S2LO+a_row,
                    smb+NOFF_W+69632+b_row, smb+NOFF_W+104448+b_row);
        __syncthreads();     // Wout slots + mid free

        if (cc<3){ fetch_wout(cc+1); CP_COMMIT(); }  // overlaps next GEMM1
    }

    {
        int r0 = wm*16 + (lane>>2);
#pragma unroll
        for (int j=0;j<4;++j){
            int c = wn*32 + j*8 + 2*(lane&3);
#pragma unroll
            for (int half=0; half<2; ++half){
                int r = r0 + half*8;
                size_t gi = (size_t)(rowbase+r)*Hc + c;
                __nv_bfloat162 hh = *reinterpret_cast<__nv_bfloat162*>(sm+NOFF_HHI+r*272+c*2);
                __nv_bfloat162 hl = *reinterpret_cast<__nv_bfloat162*>(sm+NOFF_HLO+r*272+c*2);
                float h0 = __bfloat162float(hh.x)+__bfloat162float(hl.x);
                float h1 = __bfloat162float(hh.y)+__bfloat162float(hl.y);
                float mv = mvs[r];
                out[gi]   = (h0 + accO[j][2*half]   + bouts[c])  * mv;
                out[gi+1] = (h1 + accO[j][2*half+1] + bouts[c+1])* mv;
            }
        }
    }
}

// ---------------- launch ----------------
extern "C" void kernel_launch(void* const* d_in, const int* in_sizes, int n_in,
                              void* d_out, int out_size){
    (void)in_sizes; (void)n_in; (void)out_size;
    const float* hV   =(const float*)d_in[0];
    const float* hE   =(const float*)d_in[1];
    const int*   eidx =(const int*)d_in[2];
    const float* maskV=(const float*)d_in[3];
    const float* mAtt =(const float*)d_in[4];
    const float* W1   =(const float*)d_in[5];
    const float* b1   =(const float*)d_in[6];
    const float* W2   =(const float*)d_in[7];
    const float* b2   =(const float*)d_in[8];
    const float* W3   =(const float*)d_in[9];
    const float* b3   =(const float*)d_in[10];
    const float* Win  =(const float*)d_in[11];
    const float* binp =(const float*)d_in[12];
    const float* Wout =(const float*)d_in[13];
    const float* boutp=(const float*)d_in[14];
    float* out=(float*)d_out;

    cudaFuncSetAttribute(pre1_kernel, cudaFuncAttributeMaxDynamicSharedMemorySize, P1_SMEM);
    cudaFuncSetAttribute(edge_mlp_mma, cudaFuncAttributeMaxDynamicSharedMemorySize, EDGE_SMEM);
    cudaFuncSetAttribute(node_kernel, cudaFuncAttributeMaxDynamicSharedMemorySize, NODE_SMEM);

    pre1_kernel<<<NODES/32, 256, P1_SMEM>>>(hV, W1, b1, mAtt);
    edge_mlp_mma<<<148, 512, EDGE_SMEM>>>(hE, eidx, mAtt, W1, b2, W2, W3, Win, Wout);
    node_kernel<<<NODES/64, 512, NODE_SMEM>>>(hV, maskV, b3, binp, boutp, out);
}